// round 13
// baseline (speedup 1.0000x reference)
#include <cuda_runtime.h>
#include <cuda_bf16.h>
#include <math.h>

#define BN 64
#define HN 512
#define WN 512
#define HWN 262144
#define NBGC 78643
#define CAPR 8192
#define CAPF 131072
#define CAPP 16384
#define UBITS0 0x3F7C0000u  // bits of 0.984375f
#define UBITS1 0x3F400000u  // bits of 0.75f
#define CUT0F 0.984375f
#define CUT1F 0.75f
#define MARG 1e-5f

typedef unsigned long long ull;
typedef unsigned int u32;
typedef unsigned char u8;

__device__ ull g_pre[BN][4096];
__device__ ull g_er [BN][4096];
__device__ u32 g_hist[BN][64];
__device__ int g_done1[BN];
__device__ int g_BbC[BN], g_needB[BN], g_nfg[BN];
__device__ ull g_recB[BN][CAPR];
__device__ int g_nB[BN];
__device__ ull g_recF[BN][CAPF];
__device__ ull g_vkF[BN][CAPF];
__device__ int g_nF[BN];
__device__ ull g_p1[BN][CAPP];
__device__ int g_np1[BN];
__device__ ull g_skB[BN][CAPR];
__device__ ull g_skF[BN][CAPF];   // fg score scratch + fg fallback scratch
__device__ int g_flag[2][BN];
__device__ ull g_seed[2][BN][4096];

__device__ __forceinline__ int vbin(float cam, float* vout, u32* vbits) {
    float v = __fadd_rn(cam, 1e-8f);
    *vout = v; *vbits = __float_as_uint(v);
    int k = (int)__fmul_rn(v, 64.0f);
    return k > 63 ? 63 : k;
}
__device__ __forceinline__ u32 fmono(float f) {
    u32 b = __float_as_uint(f);
    return (b & 0x80000000u) ? ~b : (b | 0x80000000u);
}
__device__ __forceinline__ float fmono_inv(u32 m) {
    u32 b = (m & 0x80000000u) ? (m ^ 0x80000000u) : ~m;
    return __uint_as_float(b);
}
__device__ __forceinline__ void mark_seed(ull* s, int pix) {
    atomicOr(&s[(pix >> 9) * 8 + ((pix & 511) >> 6)], 1ull << (pix & 63));
}

__device__ __forceinline__ ull radix_kth_largest(const ull* __restrict__ list,
                                                 int cnt, int need) {
    __shared__ u32 rh[256];
    __shared__ ull s_pref; __shared__ int s_nd;
    int tid = threadIdx.x;
    if (tid == 0) { s_pref = 0ull; s_nd = need; }
    __syncthreads();
    for (int by = 7; by >= 0; --by) {
        for (int j = tid; j < 256; j += 256) rh[j] = 0;
        __syncthreads();
        ull mask = (by == 7) ? 0ull : (~0ull << (8 * (by + 1)));
        ull pref = s_pref;
        for (int i = tid; i < cnt; i += 256) {
            ull k = list[i];
            if (((k ^ pref) & mask) == 0ull)
                atomicAdd(&rh[(int)((k >> (8 * by)) & 255ull)], 1u);
        }
        __syncthreads();
        if (tid == 0) {
            int nd = s_nd, cum = 0, sel = 0;
            for (int v = 255; v >= 0; --v) {
                u32 c = rh[v];
                if (cum + (int)c >= nd) { sel = v; s_nd = nd - cum; break; }
                cum += c;
            }
            s_pref = pref | (((ull)sel) << (8 * by));
        }
        __syncthreads();
    }
    return s_pref;
}

__device__ __forceinline__ void emit4_1(ull* __restrict__ arr, int* ctr,
                                        const bool* p, const ull* pay, int cap) {
    int lane = threadIdx.x & 31;
    u32 lt = (1u << lane) - 1u;
    u32 m0 = __ballot_sync(~0u, p[0]), m1 = __ballot_sync(~0u, p[1]);
    u32 m2 = __ballot_sync(~0u, p[2]), m3 = __ballot_sync(~0u, p[3]);
    int c0 = __popc(m0), c01 = c0 + __popc(m1), c012 = c01 + __popc(m2);
    int tot = c012 + __popc(m3);
    if (!tot) return;
    int base = 0;
    if (lane == 0) base = atomicAdd(ctr, tot);
    base = __shfl_sync(~0u, base, 0);
    if (p[0]) { int j = base + __popc(m0 & lt);         if (j < cap) arr[j] = pay[0]; }
    if (p[1]) { int j = base + c0  + __popc(m1 & lt);   if (j < cap) arr[j] = pay[1]; }
    if (p[2]) { int j = base + c01 + __popc(m2 & lt);   if (j < cap) arr[j] = pay[2]; }
    if (p[3]) { int j = base + c012 + __popc(m3 & lt);  if (j < cap) arr[j] = pay[3]; }
}
__device__ __forceinline__ void emit4_2(ull* __restrict__ a1, ull* __restrict__ a2,
                                        int* ctr, const bool* p,
                                        const ull* y1, const ull* y2, int cap) {
    int lane = threadIdx.x & 31;
    u32 lt = (1u << lane) - 1u;
    u32 m0 = __ballot_sync(~0u, p[0]), m1 = __ballot_sync(~0u, p[1]);
    u32 m2 = __ballot_sync(~0u, p[2]), m3 = __ballot_sync(~0u, p[3]);
    int c0 = __popc(m0), c01 = c0 + __popc(m1), c012 = c01 + __popc(m2);
    int tot = c012 + __popc(m3);
    if (!tot) return;
    int base = 0;
    if (lane == 0) base = atomicAdd(ctr, tot);
    base = __shfl_sync(~0u, base, 0);
    if (p[0]) { int j = base + __popc(m0 & lt);        if (j < cap) { a1[j] = y1[0]; a2[j] = y2[0]; } }
    if (p[1]) { int j = base + c0  + __popc(m1 & lt);  if (j < cap) { a1[j] = y1[1]; a2[j] = y2[1]; } }
    if (p[2]) { int j = base + c01 + __popc(m2 & lt);  if (j < cap) { a1[j] = y1[2]; a2[j] = y2[2]; } }
    if (p[3]) { int j = base + c012 + __popc(m3 & lt); if (j < cap) { a1[j] = y1[3]; a2[j] = y2[3]; } }
}

__global__ void k_zero() {
    int i = blockIdx.x * blockDim.x + threadIdx.x;
    int stride = gridDim.x * blockDim.x;
    ull* seeds = &g_seed[0][0][0];
    for (int j = i; j < 2 * BN * 4096; j += stride) seeds[j] = 0ull;
    u32* h = &g_hist[0][0];
    for (int j = i; j < BN * 64; j += stride) h[j] = 0;
    if (i < BN) {
        g_done1[i] = 0; g_nB[i] = 0; g_nF[i] = 0; g_np1[i] = 0;
        g_flag[0][i] = 0; g_flag[1][i] = 0;
    }
}

// role-split: blocks <1024 prep(x); blocks >=1024 bg-emit(ubg)
__global__ void __launch_bounds__(256) k_front(const float* __restrict__ x,
                                               const float* __restrict__ rt,
                                               const float* __restrict__ ubg) {
    __shared__ u8 sc[256 * 68];
    int tid = threadIdx.x, lane = tid & 31;
    if (blockIdx.x < 1024) {
        int b = blockIdx.x >> 4, chunk = blockIdx.x & 15;
        for (int j = tid; j < 256 * 68 / 4; j += 256) ((u32*)sc)[j] = 0;
        float th = rt[b];
        float thA = (th == 0.0f) ? 1.0f : ((th == 255.0f) ? 254.0f : th);
        float cut = thA + 1.0f;   // floor(cam*255) > thA  <=>  cam*255 >= thA+1 (thA integer)
        const float4* xb4 = (const float4*)(x + (size_t)b * HWN);
        u32* bm = (u32*)g_pre[b];
        int base = chunk * 4096;
        __syncthreads();
        for (int it = 0; it < 16; it++) {
            int gf4 = base + it * 256 + tid;
            float4 xv = xb4[gf4];
            float e[4] = {xv.x, xv.y, xv.z, xv.w};
            u32 nib = 0;
#pragma unroll
            for (int k = 0; k < 4; k++) {
                float v; u32 vb;
                sc[tid * 68 + vbin(e[k], &v, &vb)]++;
                if (__fmul_rn(e[k], 255.0f) >= cut) nib |= (1u << k);
            }
            u32 vv = nib << (4 * (lane & 7));
            vv |= __shfl_xor_sync(~0u, vv, 1);
            vv |= __shfl_xor_sync(~0u, vv, 2);
            vv |= __shfl_xor_sync(~0u, vv, 4);
            if ((lane & 7) == 0) bm[gf4 >> 3] = vv;
        }
        __syncthreads();
        if (tid < 64) {
            u32 s = 0;
            for (int t2 = 0; t2 < 256; t2++) s += sc[t2 * 68 + tid];
            if (s) atomicAdd(&g_hist[b][tid], s);
        }
        __syncthreads();
        if (tid == 0) {
            __threadfence();
            int d = atomicAdd(&g_done1[b], 1);
            if (d == 15) {
                int cum = 0, Bb = 64, nd = 0, nz = 0;
                for (int j = 0; j < 64; j++) {
                    int c = (int)atomicAdd(&g_hist[b][j], 0u);
                    if (c) nz++;
                    if (Bb == 64 && cum + c >= NBGC) { Bb = j; nd = NBGC - cum; }
                    cum += c;
                }
                g_BbC[b] = Bb; g_needB[b] = nd;
                if (nz <= 1) { g_flag[0][b] = 1; g_flag[1][b] = 1; }  // deg suspect
            }
        }
    } else {
        int b = (blockIdx.x - 1024) >> 4, chunk = (blockIdx.x - 1024) & 15;
        const float4* ub4 = (const float4*)(ubg + (size_t)b * HWN);
        int base = chunk * 4096;
        for (int it = 0; it < 16; it++) {
            int gf4 = base + it * 256 + tid;
            float4 uv = ub4[gf4];
            float e[4] = {uv.x, uv.y, uv.z, uv.w};
            bool p[4]; ull pay[4];
#pragma unroll
            for (int k = 0; k < 4; k++) {
                u32 ub = __float_as_uint(e[k]);
                p[k] = ub >= UBITS0;
                pay[k] = (((ull)ub) << 32) | (u32)(gf4 * 4 + k);
            }
            emit4_1(g_recB[b], &g_nB[b], p, pay, CAPR);
        }
    }
}

__global__ void __launch_bounds__(1024) k_erode() {
    extern __shared__ ull dsm[];
    ull* s_pre = dsm; ull* s_hb = dsm + 4096;
    __shared__ int red[32];
    int b = blockIdx.x, tid = threadIdx.x, lane = tid & 31;
    for (int i = tid; i < 4096; i += 1024) s_pre[i] = g_pre[b][i];
    __syncthreads();
    for (int i = tid; i < 4096; i += 1024) {
        int w = i & 7;
        ull av = s_pre[i];
        ull lo = w ? s_pre[i - 1] : ~0ull;
        ull hi = (w < 7) ? s_pre[i + 1] : ~0ull;
        ull r = av;
#pragma unroll
        for (int d = 1; d <= 5; d++)
            r &= ((av >> d) | (hi << (64 - d))) & ((av << d) | (lo >> (64 - d)));
        s_hb[i] = r;
    }
    __syncthreads();
    int pc = 0;
    for (int i = tid; i < 4096; i += 1024) {
        int row = i >> 3, w = i & 7;
        ull r = ~0ull;
#pragma unroll
        for (int d = -5; d <= 5; d++) {
            int rr = row + d;
            if (rr >= 0 && rr < HN) r &= s_hb[rr * 8 + w];
        }
        g_er[b][i] = r;
        pc += __popcll(r);
    }
    for (int o = 16; o; o >>= 1) pc += __shfl_down_sync(~0u, pc, o);
    if (lane == 0) red[tid >> 5] = pc;
    __syncthreads();
    if (tid == 0) {
        int c = 0;
        for (int w = 0; w < 32; w++) c += red[w];
        g_nfg[b] = (int)floorf(0.3f * (float)c);
    }
}

// x pass: bg boundary keys (bin==Bb) + fg records for roi pixels
__global__ void __launch_bounds__(256) k_mid(const float* __restrict__ x,
                                             const float* __restrict__ ufg) {
    int b = blockIdx.x >> 4, chunk = blockIdx.x & 15;
    int tid = threadIdx.x;
    int Bb = g_BbC[b];
    bool doFg = g_nfg[b] > 0;
    const float4* xb4 = (const float4*)(x + (size_t)b * HWN);
    const float4* uf4 = (const float4*)(ufg + (size_t)b * HWN);
    const u32* erw = (const u32*)g_er[b];
    int base = chunk * 4096;
    for (int it = 0; it < 16; it++) {
        int gf4 = base + it * 256 + tid;
        float4 xv = xb4[gf4];
        float e[4] = {xv.x, xv.y, xv.z, xv.w};
        u32 vb[4]; int bin[4];
#pragma unroll
        for (int k = 0; k < 4; k++) { float v; bin[k] = vbin(e[k], &v, &vb[k]); }
        {
            bool p[4]; ull pay[4];
#pragma unroll
            for (int k = 0; k < 4; k++) {
                p[k] = (bin[k] == Bb);
                pay[k] = ~((((ull)vb[k]) << 32) | (u32)(gf4 * 4 + k));
            }
            emit4_1(g_p1[b], &g_np1[b], p, pay, CAPP);
        }
        if (doFg) {
            u32 rbits = (erw[gf4 >> 3] >> ((gf4 & 7) * 4)) & 0xFu;
            float4 uv = uf4[gf4];
            float eu[4] = {uv.x, uv.y, uv.z, uv.w};
            bool p[4]; ull y1[4], y2[4];
#pragma unroll
            for (int k = 0; k < 4; k++) {
                int pix = gf4 * 4 + k;
                p[k] = (rbits >> k) & 1;
                y1[k] = (((ull)__float_as_uint(eu[k])) << 32) | (u32)pix;
                y2[k] = (((ull)vb[k]) << 32) | (u32)(HWN - 1 - pix);
            }
            emit4_2(g_recF[b], g_vkF[b], &g_nF[b], p, y1, y2, CAPF);
        }
    }
}

__global__ void __launch_bounds__(256) k_topk(const float* __restrict__ x) {
    __shared__ int s_cnt;
    int b = blockIdx.x, side = blockIdx.y;   // 0=fg, 1=bg
    int tid = threadIdx.x;
    if (g_flag[side][b]) return;
    const float* xb = x + (size_t)b * HWN;
    if (side == 1) {
        const int K = 100;
        int N = g_nB[b], np = g_np1[b];
        if (N > CAPR || np > CAPP) { if (tid == 0) g_flag[1][b] = 1; return; }
        int need = g_needB[b], Bb = g_BbC[b];
        ull T = 0ull;   // key>=0 always true if need<=0 (cannot happen)
        if (need > 0) T = radix_kth_largest(g_p1[b], np, need);
        if (tid == 0) s_cnt = 0;
        __syncthreads();
        for (int i = tid; i < N; i += 256) {
            ull r = g_recB[b][i];
            int pix = (int)(r & 0xFFFFFFFFull);
            float v; u32 vbits;
            int bin = vbin(xb[pix], &v, &vbits);
            bool cand = (bin < Bb) ||
                        (bin == Bb && (~((((ull)vbits) << 32) | (u32)pix)) >= T);
            if (cand) {
                float u = __uint_as_float((u32)(r >> 32));
                float s = logf(fmaxf(1.0f - v, 0.0f) + 1e-8f) - logf(-logf(u));
                int pos = atomicAdd(&s_cnt, 1);
                g_skB[b][pos] = (((ull)fmono(s)) << 32) | (u32)(HWN - 1 - pix);
            }
        }
        __syncthreads();
        int cnt = s_cnt;
        if (cnt < K) { if (tid == 0) g_flag[1][b] = 1; return; }
        ull Ts = radix_kth_largest(g_skB[b], cnt, K);
        float sK = fmono_inv((u32)(Ts >> 32));
        if (!(sK > -logf(-logf(CUT0F)) + MARG)) { if (tid == 0) g_flag[1][b] = 1; return; }
        ull* seed = g_seed[1][b];
        for (int i = tid; i < cnt; i += 256) {
            ull k = g_skB[b][i];
            if (k >= Ts) mark_seed(seed, HWN - 1 - (int)(k & 0xFFFFFFFFull));
        }
    } else {
        int nfg = g_nfg[b];
        int K = nfg < 100 ? nfg : 100;
        if (K <= 0) return;
        int N = g_nF[b];
        if (N > CAPF) { if (tid == 0) g_flag[0][b] = 1; return; }
        ull Tf = radix_kth_largest(g_vkF[b], N, nfg);
        for (int tier = 0; tier < 3; tier++) {
            u32 ucut = (tier == 0) ? UBITS0 : (tier == 1) ? UBITS1 : 0u;
            if (tid == 0) s_cnt = 0;
            __syncthreads();
            for (int i = tid; i < N; i += 256) {
                ull r = g_recF[b][i];
                u32 ubits = (u32)(r >> 32);
                if (ubits >= ucut) {
                    ull vk = g_vkF[b][i];
                    if (vk >= Tf) {
                        float v = __uint_as_float((u32)(vk >> 32));
                        float u = __uint_as_float(ubits);
                        float s = logf(v) - logf(-logf(u));
                        int pos = atomicAdd(&s_cnt, 1);
                        g_skF[b][pos] = (((ull)fmono(s)) << 32) | (vk & 0xFFFFFFFFull);
                    }
                }
            }
            __syncthreads();
            int cnt = s_cnt;
            bool ok = false; ull Ts = 0;
            if (cnt >= K) {
                Ts = radix_kth_largest(g_skF[b], cnt, K);
                if (tier == 2) ok = true;
                else {
                    float sK = fmono_inv((u32)(Ts >> 32));
                    float gc = (tier == 0) ? -logf(-logf(CUT0F)) : -logf(-logf(CUT1F));
                    ok = (sK > gc + MARG);
                }
            }
            if (ok) {
                ull* seed = g_seed[0][b];
                for (int i = tid; i < cnt; i += 256) {
                    ull k = g_skF[b][i];
                    if (k >= Ts) mark_seed(seed, HWN - 1 - (int)(k & 0xFFFFFFFFull));
                }
                return;
            }
            __syncthreads();
        }
        if (tid == 0) g_flag[0][b] = 1;
    }
}

// exact full redo for flagged (img,side); normally immediate return
__global__ void __launch_bounds__(256) k_fallback(const float* __restrict__ x,
                                                  const float* __restrict__ ufg,
                                                  const float* __restrict__ ubg) {
    __shared__ u32 rh[256];
    __shared__ ull s_pref; __shared__ int s_nd, s_cnt;
    __shared__ u32 smn[8], smx[8];
    int b = blockIdx.x, side = blockIdx.y;
    if (!g_flag[side][b]) return;
    int tid = threadIdx.x, lane = tid & 31;
    const float* xb = x + (size_t)b * HWN;
    const float* uu = (side ? ubg : ufg) + (size_t)b * HWN;
    const ull* roi = g_er[b];
    u32 mn = 0xFFFFFFFFu, mx = 0u;
    for (int pix = tid; pix < HWN; pix += 256) {
        u32 cb = __float_as_uint(xb[pix]);
        mn = min(mn, cb); mx = max(mx, cb);
    }
    for (int o = 16; o; o >>= 1) {
        mn = min(mn, __shfl_down_sync(~0u, mn, o));
        mx = max(mx, __shfl_down_sync(~0u, mx, o));
    }
    if (lane == 0) { smn[tid >> 5] = mn; smx[tid >> 5] = mx; }
    __syncthreads();
    mn = smn[0]; mx = smx[0];
    for (int w = 1; w < 8; w++) { mn = min(mn, smn[w]); mx = max(mx, smx[w]); }
    if (mn == mx) return;   // degenerate: no seeds
    int K, target;
    if (side == 0) {
        int nfg = g_nfg[b];
        K = nfg < 100 ? nfg : 100;
        target = nfg;
        if (K <= 0) return;
    } else { K = 100; target = NBGC; }
    if (tid == 0) { s_pref = 0ull; s_nd = target; }
    __syncthreads();
    for (int by = 7; by >= 0; --by) {
        for (int j = tid; j < 256; j += 256) rh[j] = 0;
        __syncthreads();
        ull mask = (by == 7) ? 0ull : (~0ull << (8 * (by + 1)));
        ull pref = s_pref;
        for (int pix = tid; pix < HWN; pix += 256) {
            if (side == 0 && !((roi[(pix >> 9) * 8 + ((pix & 511) >> 6)] >> (pix & 63)) & 1ull))
                continue;
            float v; u32 vbits;
            vbin(xb[pix], &v, &vbits);
            ull key = side ? ~((((ull)vbits) << 32) | (u32)pix)
                           : ((((ull)vbits) << 32) | (u32)(HWN - 1 - pix));
            if (((key ^ pref) & mask) == 0ull)
                atomicAdd(&rh[(int)((key >> (8 * by)) & 255ull)], 1u);
        }
        __syncthreads();
        if (tid == 0) {
            int nd = s_nd, cum = 0, sel = 0;
            for (int v = 255; v >= 0; --v) {
                u32 c = rh[v];
                if (cum + (int)c >= nd) { sel = v; s_nd = nd - cum; break; }
                cum += c;
            }
            s_pref = s_pref | (((ull)sel) << (8 * by));
        }
        __syncthreads();
    }
    ull Tc = s_pref;
    if (tid == 0) s_cnt = 0;
    __syncthreads();
    for (int pix = tid; pix < HWN; pix += 256) {
        if (side == 0 && !((roi[(pix >> 9) * 8 + ((pix & 511) >> 6)] >> (pix & 63)) & 1ull))
            continue;
        float v; u32 vbits;
        vbin(xb[pix], &v, &vbits);
        ull key = side ? ~((((ull)vbits) << 32) | (u32)pix)
                       : ((((ull)vbits) << 32) | (u32)(HWN - 1 - pix));
        if (key >= Tc) {
            float u = uu[pix];
            float p = side ? (fmaxf(1.0f - v, 0.0f) + 1e-8f) : v;
            float s = logf(p) - logf(-logf(u));
            int pos = atomicAdd(&s_cnt, 1);
            g_skF[b][pos] = (((ull)fmono(s)) << 32) | (u32)(HWN - 1 - pix);
        }
    }
    __syncthreads();
    int cnt = s_cnt;
    ull Ts = radix_kth_largest(g_skF[b], cnt, K);
    ull* seed = g_seed[side][b];
    for (int i = tid; i < cnt; i += 256) {
        ull k = g_skF[b][i];
        if (k >= Ts) mark_seed(seed, HWN - 1 - (int)(k & 0xFFFFFFFFull));
    }
}

// 3x3 dilation + compose; 16-row bands, float4 stores
__global__ void __launch_bounds__(256) k_output(float* __restrict__ out) {
    __shared__ ull sv[2][16][8], sh[2][16][8];
    int b = blockIdx.x >> 5, band = blockIdx.x & 31, r0 = band * 16;
    int t = threadIdx.x;
    {
        int side = t >> 7, rr = (t >> 3) & 15, w = t & 7;
        int r = r0 + rr;
        const ull* sd = g_seed[side][b];
        ull v = sd[r * 8 + w];
        if (r > 0)   v |= sd[(r - 1) * 8 + w];
        if (r < 511) v |= sd[(r + 1) * 8 + w];
        sv[side][rr][w] = v;
    }
    __syncthreads();
    {
        int side = t >> 7, rr = (t >> 3) & 15, w = t & 7;
        ull m = sv[side][rr][w];
        ull h = m | (m << 1) | (m >> 1);
        if (w > 0) h |= sv[side][rr][w - 1] >> 63;
        if (w < 7) h |= sv[side][rr][w + 1] << 63;
        sh[side][rr][w] = h;
    }
    __syncthreads();
    int rr = t >> 4, c0 = (t & 15) * 32;
    int w = c0 >> 6, half = c0 & 32;
    u32 fb = (u32)(sh[0][rr][w] >> half);
    u32 gb = (u32)(sh[1][rr][w] >> half);
    float4* o4 = (float4*)(out + (size_t)b * HWN + (size_t)(r0 + rr) * WN + c0);
#pragma unroll
    for (int j = 0; j < 8; j++) {
        float vv[4];
#pragma unroll
        for (int k = 0; k < 4; k++) {
            int bit = j * 4 + k;
            int f = (fb >> bit) & 1, g = (gb >> bit) & 1;
            vv[k] = (f && !g) ? 1.0f : ((g && !f) ? 0.0f : -255.0f);
        }
        o4[j] = make_float4(vv[0], vv[1], vv[2], vv[3]);
    }
}

extern "C" void kernel_launch(void* const* d_in, const int* in_sizes, int n_in,
                              void* d_out, int out_size) {
    (void)out_size;
    const float* big[3] = {nullptr, nullptr, nullptr};
    const float* rt = nullptr;
    int nb = 0;
    for (int i = 0; i < n_in && i < 4; i++) {
        if (in_sizes[i] == BN) rt = (const float*)d_in[i];
        else if (nb < 3)       big[nb++] = (const float*)d_in[i];
    }
    const float* x   = big[0];
    const float* ufg = big[1];
    const float* ubg = big[2];
    float* out = (float*)d_out;

    cudaFuncSetAttribute(k_erode, cudaFuncAttributeMaxDynamicSharedMemorySize, 65536);

    k_zero<<<512, 256>>>();
    k_front<<<2048, 256>>>(x, rt, ubg);
    k_erode<<<BN, 1024, 65536>>>();
    k_mid<<<1024, 256>>>(x, ufg);
    k_topk<<<dim3(BN, 2), 256>>>(x);
    k_fallback<<<dim3(BN, 2), 256>>>(x, ufg, ubg);
    k_output<<<2048, 256>>>(out);
}

// round 14
// speedup vs baseline: 2.1103x; 2.1103x over previous
#include <cuda_runtime.h>
#include <cuda_bf16.h>
#include <math.h>

#define BN    64
#define HN    512
#define WN    512
#define HWN   262144
#define NBGC  78643
#define CAPP  16384
#define CAPC  79872

#define UCUT0 0xBF7C0000u   // fmono(0.984375f)
#define UCUT1 0xBF400000u   // fmono(0.75f)

typedef unsigned long long ull;
typedef unsigned int       u32;
typedef unsigned char      u8;

__device__ ull g_pre[BN][HN * 8];
__device__ ull g_er [BN][HN * 8];
__device__ u32 g_ch_all[BN][64];
__device__ u32 g_ch_roi[BN][64];
__device__ u32 g_minb[BN], g_maxb[BN];
__device__ int g_nfg[BN], g_deg[BN];
__device__ int g_BbC[BN], g_needB[BN];
__device__ int g_BfC[BN], g_needF[BN];
__device__ int g_done1[BN], g_done2[BN];
__device__ ull g_rec[2][BN][CAPC];    // candidate records (fmono(u)<<32)|pix
__device__ int g_n[2][BN];
__device__ ull g_p1[2][BN][CAPP];     // stage-1 boundary value keys
__device__ ull g_pr[2][BN][CAPP];     // matching records
__device__ int g_np[2][BN];
__device__ ull g_sk[2][BN][CAPC];     // score-key scratch
__device__ ull g_seed[2][BN][HN * 8];

__device__ __forceinline__ int cbin(float v) {
    int k = (int)(v * 64.0f);
    return k > 63 ? 63 : k;
}
__device__ __forceinline__ u32 fmono(float f) {
    u32 b = __float_as_uint(f);
    return (b & 0x80000000u) ? ~b : (b | 0x80000000u);
}
__device__ __forceinline__ float fmono_inv(u32 m) {
    u32 b = (m & 0x80000000u) ? (m ^ 0x80000000u) : ~m;
    return __uint_as_float(b);
}
__device__ __forceinline__ void mark_seed(ull* seedimg, int pix) {
    atomicOr(&seedimg[(pix >> 9) * 8 + ((pix & 511) >> 6)], 1ull << (pix & 63));
}

// exact m-th largest 64-bit key among list[0..cnt) (block-collective)
__device__ __forceinline__ ull radix_kth_largest(const ull* __restrict__ list,
                                                 int cnt, int need) {
    __shared__ u32 rh[256];
    __shared__ ull s_pref;
    __shared__ int s_nd;
    int tid = threadIdx.x;
    if (tid == 0) { s_pref = 0ull; s_nd = need; }
    __syncthreads();
    for (int by = 7; by >= 0; --by) {
        for (int j = tid; j < 256; j += blockDim.x) rh[j] = 0;
        __syncthreads();
        ull mask = (by == 7) ? 0ull : (~0ull << (8 * (by + 1)));
        ull pref = s_pref;
        for (int i = tid; i < cnt; i += blockDim.x) {
            ull k = list[i];
            if (((k ^ pref) & mask) == 0ull)
                atomicAdd(&rh[(int)((k >> (8 * by)) & 255ull)], 1u);
        }
        __syncthreads();
        if (tid == 0) {
            int nd = s_nd; int cum = 0; int sel = 0;
            for (int v = 255; v >= 0; --v) {
                u32 c = rh[v];
                if (cum + (int)c >= nd) { sel = v; s_nd = nd - cum; break; }
                cum += c;
            }
            s_pref = pref | (((ull)sel) << (8 * by));
        }
        __syncthreads();
    }
    return s_pref;
}

__global__ void k_zero() {
    int i = blockIdx.x * blockDim.x + threadIdx.x;
    int stride = gridDim.x * blockDim.x;
    ull* seeds = &g_seed[0][0][0];
    for (int j = i; j < 2 * BN * HN * 8; j += stride) seeds[j] = 0ull;
    u32* h1 = &g_ch_all[0][0];
    u32* h2 = &g_ch_roi[0][0];
    for (int j = i; j < BN * 64; j += stride) { h1[j] = 0; h2[j] = 0; }
    if (i < BN) {
        g_n[0][i] = 0;  g_n[1][i] = 0;
        g_np[0][i] = 0; g_np[1][i] = 0;
        g_done1[i] = 0; g_done2[i] = 0;
        g_minb[i] = 0xFFFFFFFFu; g_maxb[i] = 0u;
    }
}

// P1: x -> pre-erosion bitmap, minmax, 64-bin value hist; ticketed bg scan
__global__ void __launch_bounds__(256) k_prep(const float* __restrict__ x,
                                              const float* __restrict__ rt) {
    __shared__ u8 sc[256 * 68];
    __shared__ u32 smn[8], smx[8];
    int b = blockIdx.x >> 4;
    int chunk = blockIdx.x & 15;
    int tid = threadIdx.x, lane = tid & 31;
    for (int j = tid; j < 256 * 68 / 4; j += 256) ((u32*)sc)[j] = 0;
    float th = rt[b];
    float thA = (th == 0.0f) ? 1.0f : ((th == 255.0f) ? 254.0f : th);
    u32 mn = 0xFFFFFFFFu, mx = 0u;
    const float4* xb4 = (const float4*)(x + (size_t)b * HWN);
    u32* bm = (u32*)g_pre[b];
    int base = chunk * 4096;
    __syncthreads();
    for (int it = 0; it < 16; it++) {
        int gf4 = base + it * 256 + tid;
        float4 xv = xb4[gf4];
        float e[4] = {xv.x, xv.y, xv.z, xv.w};
        u32 nib = 0;
#pragma unroll
        for (int k = 0; k < 4; k++) {
            float cam = e[k];
            u32 cb2 = __float_as_uint(cam);
            mn = min(mn, cb2); mx = max(mx, cb2);
            sc[tid * 68 + cbin(cam + 1e-8f)]++;
            if (floorf(cam * 255.0f) > thA) nib |= (1u << k);
        }
        u32 vv = nib << (4 * (lane & 7));
        vv |= __shfl_xor_sync(0xFFFFFFFFu, vv, 1);
        vv |= __shfl_xor_sync(0xFFFFFFFFu, vv, 2);
        vv |= __shfl_xor_sync(0xFFFFFFFFu, vv, 4);
        if ((lane & 7) == 0) bm[gf4 >> 3] = vv;
    }
    __syncthreads();
    if (tid < 64) {
        u32 s = 0;
        for (int t2 = 0; t2 < 256; t2++) s += sc[t2 * 68 + tid];
        if (s) atomicAdd(&g_ch_all[b][tid], s);
    }
    for (int o = 16; o; o >>= 1) {
        mn = min(mn, __shfl_down_sync(0xFFFFFFFFu, mn, o));
        mx = max(mx, __shfl_down_sync(0xFFFFFFFFu, mx, o));
    }
    if (lane == 0) { smn[tid >> 5] = mn; smx[tid >> 5] = mx; }
    __syncthreads();
    if (tid == 0) {
        for (int w = 1; w < 8; w++) { mn = min(mn, smn[w]); mx = max(mx, smx[w]); }
        atomicMin(&g_minb[b], mn);
        atomicMax(&g_maxb[b], mx);
        __threadfence();
        int d = atomicAdd(&g_done1[b], 1);
        if (d == 15) {
            u32 mnv = atomicMin(&g_minb[b], 0xFFFFFFFFu);
            u32 mxv = atomicMax(&g_maxb[b], 0u);
            g_deg[b] = (mnv == mxv) ? 1 : 0;
            int cum = 0, Bb = 64, nd = 0;
            for (int j = 0; j < 64; j++) {
                int c = (int)atomicAdd(&g_ch_all[b][j], 0u);
                if (cum + c >= NBGC) { Bb = j; nd = NBGC - cum; break; }
                cum += c;
            }
            g_BbC[b] = Bb; g_needB[b] = nd;
        }
    }
}

// P2: 11x11 erosion (bit-packed, OOB=1) + roi popcount -> n_fg
__global__ void __launch_bounds__(1024) k_erode() {
    extern __shared__ ull dsm[];
    ull* s_pre = dsm;
    ull* s_hb  = dsm + 4096;
    __shared__ int red[32];
    int b = blockIdx.x, tid = threadIdx.x, lane = tid & 31;
    for (int i = tid; i < 4096; i += 1024) s_pre[i] = g_pre[b][i];
    __syncthreads();
    for (int i = tid; i < 4096; i += 1024) {
        int w = i & 7;
        ull av = s_pre[i];
        ull lo = w ? s_pre[i - 1] : ~0ull;
        ull hi = (w < 7) ? s_pre[i + 1] : ~0ull;
        ull r = av;
#pragma unroll
        for (int d = 1; d <= 5; d++)
            r &= ((av >> d) | (hi << (64 - d))) & ((av << d) | (lo >> (64 - d)));
        s_hb[i] = r;
    }
    __syncthreads();
    int pc = 0;
    for (int i = tid; i < 4096; i += 1024) {
        int row = i >> 3, w = i & 7;
        ull r = ~0ull;
#pragma unroll
        for (int d = -5; d <= 5; d++) {
            int rr = row + d;
            if (rr >= 0 && rr < HN) r &= s_hb[rr * 8 + w];
        }
        g_er[b][i] = r;
        pc += __popcll(r);
    }
    for (int o = 16; o; o >>= 1) pc += __shfl_down_sync(0xFFFFFFFFu, pc, o);
    if (lane == 0) red[tid >> 5] = pc;
    __syncthreads();
    if (tid == 0) {
        int c = 0;
        for (int w = 0; w < 32; w++) c += red[w];
        g_nfg[b] = (int)floorf(0.3f * (float)c);
    }
}

// P3: roi 64-bin value hist (skipped when n_fg==0); ticketed fg scan
__global__ void __launch_bounds__(256) k_roihist(const float* __restrict__ x) {
    __shared__ u8 sc[256 * 68];
    int b = blockIdx.x >> 4;
    int chunk = blockIdx.x & 15;
    int tid = threadIdx.x;
    int nfg = g_nfg[b];
    if (nfg > 0) {
        for (int j = tid; j < 256 * 68 / 4; j += 256) ((u32*)sc)[j] = 0;
        __syncthreads();
        const float4* xb4 = (const float4*)(x + (size_t)b * HWN);
        const u32* erw = (const u32*)g_er[b];
        int base = chunk * 4096;
        for (int it = 0; it < 16; it++) {
            int gf4 = base + it * 256 + tid;
            u32 rbits = (erw[gf4 >> 3] >> ((gf4 & 7) * 4)) & 0xFu;
            if (rbits) {
                float4 xv = xb4[gf4];
                if (rbits & 1u) sc[tid * 68 + cbin(xv.x + 1e-8f)]++;
                if (rbits & 2u) sc[tid * 68 + cbin(xv.y + 1e-8f)]++;
                if (rbits & 4u) sc[tid * 68 + cbin(xv.z + 1e-8f)]++;
                if (rbits & 8u) sc[tid * 68 + cbin(xv.w + 1e-8f)]++;
            }
        }
        __syncthreads();
        if (tid < 64) {
            u32 s = 0;
            for (int t2 = 0; t2 < 256; t2++) s += sc[t2 * 68 + tid];
            if (s) atomicAdd(&g_ch_roi[b][tid], s);
        }
        __syncthreads();
    }
    if (tid == 0) {
        __threadfence();
        int d = atomicAdd(&g_done2[b], 1);
        if (d == 15) {
            int n = g_nfg[b];
            int Bf = 64, nd = 0;
            if (n > 0) {
                int cum = 0;
                for (int j = 63; j >= 0; j--) {
                    int c = (int)atomicAdd(&g_ch_roi[b][j], 0u);
                    if (cum + c >= n) { Bf = j; nd = n - cum; break; }
                    cum += c;
                }
            }
            g_BfC[b] = Bf; g_needF[b] = nd;
        }
    }
}

// P4: streaming classify — coalesced float4 loads of x, ufg, ubg (no predication
// on the loads), emit candidate records + stage-1 boundary pairs. No logf.
__global__ void __launch_bounds__(256) k_score(const float* __restrict__ x,
                                               const float* __restrict__ ufg,
                                               const float* __restrict__ ubg) {
    int b = blockIdx.x >> 4;
    int chunk = blockIdx.x & 15;
    int tid = threadIdx.x, lane = tid & 31;
    int BbC = g_BbC[b], BfC = g_BfC[b];
    const float4* xb4 = (const float4*)(x + (size_t)b * HWN);
    const float4* uf4 = (const float4*)(ufg + (size_t)b * HWN);
    const float4* ub4 = (const float4*)(ubg + (size_t)b * HWN);
    const u32* erw = (const u32*)g_er[b];
    int base = chunk * 4096;
    u32 lt = (1u << lane) - 1u;
    for (int it = 0; it < 16; it++) {
        int gf4 = base + it * 256 + tid;
        float4 xv = xb4[gf4];
        float4 ufv = uf4[gf4];
        float4 ubv = ub4[gf4];
        u32 rbits = (erw[gf4 >> 3] >> ((gf4 & 7) * 4)) & 0xFu;
        float vx[4] = {xv.x + 1e-8f, xv.y + 1e-8f, xv.z + 1e-8f, xv.w + 1e-8f};
        float euf[4] = {ufv.x, ufv.y, ufv.z, ufv.w};
        float eub[4] = {ubv.x, ubv.y, ubv.z, ubv.w};
        bool bs[4], bb[4], fs[4], fb[4];
        ull recB[4], recF[4], keyB[4], keyF[4];
#pragma unroll
        for (int k = 0; k < 4; k++) {
            float v = vx[k];
            int c = cbin(v);
            int pix = gf4 * 4 + k;
            int roi = (rbits >> k) & 1;
            bs[k] = c < BbC;  bb[k] = (c == BbC);
            fs[k] = roi && (c > BfC);  fb[k] = roi && (c == BfC);
            recB[k] = (((ull)(__float_as_uint(eub[k]) | 0x80000000u)) << 32) | (u32)pix;
            recF[k] = (((ull)(__float_as_uint(euf[k]) | 0x80000000u)) << 32) | (u32)pix;
            u32 vb = __float_as_uint(v);
            keyB[k] = ~((((ull)vb) << 32) | (u32)pix);
            keyF[k] = (((ull)vb) << 32) | (u32)(HWN - 1 - pix);
        }
        {   // sure bg records
            u32 m0 = __ballot_sync(~0u, bs[0]), m1 = __ballot_sync(~0u, bs[1]);
            u32 m2 = __ballot_sync(~0u, bs[2]), m3 = __ballot_sync(~0u, bs[3]);
            int p0 = __popc(m0), p01 = p0 + __popc(m1), p012 = p01 + __popc(m2);
            int tot = p012 + __popc(m3);
            int bse = 0;
            if (lane == 0 && tot) bse = atomicAdd(&g_n[1][b], tot);
            bse = __shfl_sync(~0u, bse, 0);
            if (bs[0]) { int j = bse + __popc(m0 & lt);        if (j < CAPC) g_rec[1][b][j] = recB[0]; }
            if (bs[1]) { int j = bse + p0 + __popc(m1 & lt);   if (j < CAPC) g_rec[1][b][j] = recB[1]; }
            if (bs[2]) { int j = bse + p01 + __popc(m2 & lt);  if (j < CAPC) g_rec[1][b][j] = recB[2]; }
            if (bs[3]) { int j = bse + p012 + __popc(m3 & lt); if (j < CAPC) g_rec[1][b][j] = recB[3]; }
        }
        {   // sure fg records
            u32 m0 = __ballot_sync(~0u, fs[0]), m1 = __ballot_sync(~0u, fs[1]);
            u32 m2 = __ballot_sync(~0u, fs[2]), m3 = __ballot_sync(~0u, fs[3]);
            int p0 = __popc(m0), p01 = p0 + __popc(m1), p012 = p01 + __popc(m2);
            int tot = p012 + __popc(m3);
            int bse = 0;
            if (lane == 0 && tot) bse = atomicAdd(&g_n[0][b], tot);
            bse = __shfl_sync(~0u, bse, 0);
            if (fs[0]) { int j = bse + __popc(m0 & lt);        if (j < CAPC) g_rec[0][b][j] = recF[0]; }
            if (fs[1]) { int j = bse + p0 + __popc(m1 & lt);   if (j < CAPC) g_rec[0][b][j] = recF[1]; }
            if (fs[2]) { int j = bse + p01 + __popc(m2 & lt);  if (j < CAPC) g_rec[0][b][j] = recF[2]; }
            if (fs[3]) { int j = bse + p012 + __popc(m3 & lt); if (j < CAPC) g_rec[0][b][j] = recF[3]; }
        }
        {   // bg boundary pairs
            u32 m0 = __ballot_sync(~0u, bb[0]), m1 = __ballot_sync(~0u, bb[1]);
            u32 m2 = __ballot_sync(~0u, bb[2]), m3 = __ballot_sync(~0u, bb[3]);
            int p0 = __popc(m0), p01 = p0 + __popc(m1), p012 = p01 + __popc(m2);
            int tot = p012 + __popc(m3);
            int bse = 0;
            if (lane == 0 && tot) bse = atomicAdd(&g_np[1][b], tot);
            bse = __shfl_sync(~0u, bse, 0);
            if (bb[0]) { int j = bse + __popc(m0 & lt);        if (j < CAPP) { g_p1[1][b][j] = keyB[0]; g_pr[1][b][j] = recB[0]; } }
            if (bb[1]) { int j = bse + p0 + __popc(m1 & lt);   if (j < CAPP) { g_p1[1][b][j] = keyB[1]; g_pr[1][b][j] = recB[1]; } }
            if (bb[2]) { int j = bse + p01 + __popc(m2 & lt);  if (j < CAPP) { g_p1[1][b][j] = keyB[2]; g_pr[1][b][j] = recB[2]; } }
            if (bb[3]) { int j = bse + p012 + __popc(m3 & lt); if (j < CAPP) { g_p1[1][b][j] = keyB[3]; g_pr[1][b][j] = recB[3]; } }
        }
        {   // fg boundary pairs
            u32 m0 = __ballot_sync(~0u, fb[0]), m1 = __ballot_sync(~0u, fb[1]);
            u32 m2 = __ballot_sync(~0u, fb[2]), m3 = __ballot_sync(~0u, fb[3]);
            int p0 = __popc(m0), p01 = p0 + __popc(m1), p012 = p01 + __popc(m2);
            int tot = p012 + __popc(m3);
            int bse = 0;
            if (lane == 0 && tot) bse = atomicAdd(&g_np[0][b], tot);
            bse = __shfl_sync(~0u, bse, 0);
            if (fb[0]) { int j = bse + __popc(m0 & lt);        if (j < CAPP) { g_p1[0][b][j] = keyF[0]; g_pr[0][b][j] = recF[0]; } }
            if (fb[1]) { int j = bse + p0 + __popc(m1 & lt);   if (j < CAPP) { g_p1[0][b][j] = keyF[1]; g_pr[0][b][j] = recF[1]; } }
            if (fb[2]) { int j = bse + p01 + __popc(m2 & lt);  if (j < CAPP) { g_p1[0][b][j] = keyF[2]; g_pr[0][b][j] = recF[2]; } }
            if (fb[3]) { int j = bse + p012 + __popc(m3 & lt); if (j < CAPP) { g_p1[0][b][j] = keyF[3]; g_pr[0][b][j] = recF[3]; } }
        }
    }
}

// P5: stage-1 boundary refinement — append exact winners' records
__global__ void __launch_bounds__(256) k_refine1() {
    int b = blockIdx.x, side = blockIdx.y;
    int need = side ? g_needB[b] : g_needF[b];
    if (need <= 0) return;
    int cnt = g_np[side][b];
    if (cnt > CAPP) cnt = CAPP;
    ull T = radix_kth_largest(g_p1[side][b], cnt, need);
    for (int i = threadIdx.x; i < cnt; i += 256) {
        if (g_p1[side][b][i] >= T) {
            int pos = atomicAdd(&g_n[side][b], 1);
            if (pos < CAPC) g_rec[side][b][pos] = g_pr[side][b][i];
        }
    }
}

// P6: sparse exact top-K by Gumbel score with u-tier verification (1024 thr)
__global__ void __launch_bounds__(1024) k_topk(const float* __restrict__ x) {
    __shared__ int s_cnt;
    __shared__ int s_done;
    int b = blockIdx.x, side = blockIdx.y;
    int K;
    if (side == 0) {
        int nf = g_nfg[b];
        K = g_deg[b] ? 0 : (nf < 100 ? nf : 100);
    } else {
        K = g_deg[b] ? 0 : 100;
    }
    if (K <= 0) return;
    int N = g_n[side][b];
    if (N > CAPC) N = CAPC;
    const ull* recs = g_rec[side][b];
    ull* sk = g_sk[side][b];
    const float* xb = x + (size_t)b * HWN;
    int tid = threadIdx.x;
    if (tid == 0) s_done = 0;
    __syncthreads();
    for (int tier = 0; tier < 3; tier++) {
        if (s_done) break;
        u32 ucut = (tier == 0) ? UCUT0 : (tier == 1) ? UCUT1 : 0u;
        if (tid == 0) s_cnt = 0;
        __syncthreads();
        for (int i = tid; i < N; i += 1024) {
            ull r = recs[i];
            u32 uhi = (u32)(r >> 32);
            if (uhi >= ucut) {
                float u = __uint_as_float(uhi & 0x7FFFFFFFu);
                int pix = (int)(r & 0xFFFFFFFFull);
                float v = xb[pix] + 1e-8f;
                float p = side ? (fmaxf(1.0f - v, 0.0f) + 1e-8f) : v;
                float s = logf(p) - logf(-logf(u));
                int pos = atomicAdd(&s_cnt, 1);
                sk[pos] = (((ull)fmono(s)) << 32) | (u32)(HWN - 1 - pix);
            }
        }
        __syncthreads();
        int cnt = s_cnt;
        bool ok = false;
        ull T = 0;
        if (cnt >= K) {
            T = radix_kth_largest(sk, cnt, K);
            if (tier == 2) ok = true;
            else {
                float sK = fmono_inv((u32)(T >> 32));
                float edge = (tier == 0) ? 0.984375f : 0.75f;
                float gc = -logf(-logf(edge));
                ok = (sK > gc);   // excluded s <= g <= gc < sK
            }
        }
        if (ok) {
            ull* seed = g_seed[side][b];
            for (int i = tid; i < cnt; i += 1024)
                if (sk[i] >= T) mark_seed(seed, HWN - 1 - (int)(sk[i] & 0xFFFFFFFFull));
            if (tid == 0) s_done = 1;
        }
        __syncthreads();
    }
}

// P7: 3x3 dilation + compose; 16-row bands, float4 stores
__global__ void __launch_bounds__(256) k_output(float* __restrict__ out) {
    __shared__ ull sv[2][16][8], sh[2][16][8];
    int b = blockIdx.x >> 5, band = blockIdx.x & 31, r0 = band * 16;
    int t = threadIdx.x;
    {
        int side = t >> 7, rr = (t >> 3) & 15, w = t & 7;
        int r = r0 + rr;
        const ull* sd = g_seed[side][b];
        ull v = sd[r * 8 + w];
        if (r > 0)   v |= sd[(r - 1) * 8 + w];
        if (r < 511) v |= sd[(r + 1) * 8 + w];
        sv[side][rr][w] = v;
    }
    __syncthreads();
    {
        int side = t >> 7, rr = (t >> 3) & 15, w = t & 7;
        ull m = sv[side][rr][w];
        ull h = m | (m << 1) | (m >> 1);
        if (w > 0) h |= sv[side][rr][w - 1] >> 63;
        if (w < 7) h |= sv[side][rr][w + 1] << 63;
        sh[side][rr][w] = h;
    }
    __syncthreads();
    int rr = t >> 4, c0 = (t & 15) * 32;
    int w = c0 >> 6, half = c0 & 32;
    u32 fb = (u32)(sh[0][rr][w] >> half);
    u32 gb = (u32)(sh[1][rr][w] >> half);
    float4* o4 = (float4*)(out + (size_t)b * HWN + (size_t)(r0 + rr) * WN + c0);
#pragma unroll
    for (int j = 0; j < 8; j++) {
        float vv[4];
#pragma unroll
        for (int k = 0; k < 4; k++) {
            int bit = j * 4 + k;
            int f = (fb >> bit) & 1, g = (gb >> bit) & 1;
            vv[k] = (f && !g) ? 1.0f : ((g && !f) ? 0.0f : -255.0f);
        }
        o4[j] = make_float4(vv[0], vv[1], vv[2], vv[3]);
    }
}

extern "C" void kernel_launch(void* const* d_in, const int* in_sizes, int n_in,
                              void* d_out, int out_size) {
    (void)out_size;
    const float* big[3] = {nullptr, nullptr, nullptr};
    const float* rt = nullptr;
    int nb = 0;
    for (int i = 0; i < n_in && i < 4; i++) {
        if (in_sizes[i] == BN) rt = (const float*)d_in[i];
        else if (nb < 3)       big[nb++] = (const float*)d_in[i];
    }
    const float* x   = big[0];
    const float* ufg = big[1];
    const float* ubg = big[2];
    float* out = (float*)d_out;

    cudaFuncSetAttribute(k_erode, cudaFuncAttributeMaxDynamicSharedMemorySize, 65536);

    k_zero<<<512, 256>>>();
    k_prep<<<BN * 16, 256>>>(x, rt);
    k_erode<<<BN, 1024, 65536>>>();
    k_roihist<<<BN * 16, 256>>>(x);
    k_score<<<BN * 16, 256>>>(x, ufg, ubg);
    k_refine1<<<dim3(BN, 2), 256>>>();
    k_topk<<<dim3(BN, 2), 1024>>>(x);
    k_output<<<2048, 256>>>(out);
}

// round 15
// speedup vs baseline: 2.2148x; 1.0495x over previous
#include <cuda_runtime.h>
#include <cuda_bf16.h>
#include <math.h>

#define BN    64
#define HN    512
#define WN    512
#define HWN   262144
#define NBGC  78643
#define CAPP  16384
#define CAPC  79872

#define UCUT0 0xBF7C0000u   // fmono(0.984375f)
#define UCUT1 0xBF400000u   // fmono(0.75f)

typedef unsigned long long ull;
typedef unsigned int       u32;
typedef unsigned char      u8;

__device__ ull g_pre[BN][HN * 8];
__device__ ull g_er [BN][HN * 8];
__device__ u32 g_ch_all[BN][64];
__device__ u32 g_minb[BN], g_maxb[BN];
__device__ int g_nfg[BN], g_deg[BN];
__device__ int g_BbC[BN], g_needB[BN];
__device__ int g_BfC[BN], g_needF[BN];
__device__ int g_done1[BN];
__device__ ull g_rec[2][BN][CAPC];    // candidate records (fmono(u)<<32)|pix
__device__ int g_n[2][BN];
__device__ ull g_p1[2][BN][CAPP];     // stage-1 boundary value keys
__device__ ull g_pr[2][BN][CAPP];     // matching records
__device__ int g_np[2][BN];
__device__ ull g_sk[2][BN][CAPC];     // score-key scratch
__device__ ull g_seed[2][BN][HN * 8];

__device__ __forceinline__ int cbin(float v) {
    int k = (int)(v * 64.0f);
    return k > 63 ? 63 : k;
}
__device__ __forceinline__ u32 fmono(float f) {
    u32 b = __float_as_uint(f);
    return (b & 0x80000000u) ? ~b : (b | 0x80000000u);
}
__device__ __forceinline__ float fmono_inv(u32 m) {
    u32 b = (m & 0x80000000u) ? (m ^ 0x80000000u) : ~m;
    return __uint_as_float(b);
}
__device__ __forceinline__ void mark_seed(ull* seedimg, int pix) {
    atomicOr(&seedimg[(pix >> 9) * 8 + ((pix & 511) >> 6)], 1ull << (pix & 63));
}

// exact m-th largest 64-bit key among list[0..cnt) (block-collective)
__device__ __forceinline__ ull radix_kth_largest(const ull* __restrict__ list,
                                                 int cnt, int need) {
    __shared__ u32 rh[256];
    __shared__ ull s_pref;
    __shared__ int s_nd;
    int tid = threadIdx.x;
    if (tid == 0) { s_pref = 0ull; s_nd = need; }
    __syncthreads();
    for (int by = 7; by >= 0; --by) {
        for (int j = tid; j < 256; j += blockDim.x) rh[j] = 0;
        __syncthreads();
        ull mask = (by == 7) ? 0ull : (~0ull << (8 * (by + 1)));
        ull pref = s_pref;
        for (int i = tid; i < cnt; i += blockDim.x) {
            ull k = list[i];
            if (((k ^ pref) & mask) == 0ull)
                atomicAdd(&rh[(int)((k >> (8 * by)) & 255ull)], 1u);
        }
        __syncthreads();
        if (tid == 0) {
            int nd = s_nd; int cum = 0; int sel = 0;
            for (int v = 255; v >= 0; --v) {
                u32 c = rh[v];
                if (cum + (int)c >= nd) { sel = v; s_nd = nd - cum; break; }
                cum += c;
            }
            s_pref = pref | (((ull)sel) << (8 * by));
        }
        __syncthreads();
    }
    return s_pref;
}

__global__ void k_zero() {
    int i = blockIdx.x * blockDim.x + threadIdx.x;
    int stride = gridDim.x * blockDim.x;
    ull* seeds = &g_seed[0][0][0];
    for (int j = i; j < 2 * BN * HN * 8; j += stride) seeds[j] = 0ull;
    u32* h1 = &g_ch_all[0][0];
    for (int j = i; j < BN * 64; j += stride) h1[j] = 0;
    if (i < BN) {
        g_n[0][i] = 0;  g_n[1][i] = 0;
        g_np[0][i] = 0; g_np[1][i] = 0;
        g_done1[i] = 0;
        g_minb[i] = 0xFFFFFFFFu; g_maxb[i] = 0u;
    }
}

// P1: x -> pre-erosion bitmap, minmax, 64-bin value hist; ticketed bg scan
__global__ void __launch_bounds__(256) k_prep(const float* __restrict__ x,
                                              const float* __restrict__ rt) {
    __shared__ u8 sc[256 * 68];
    __shared__ u32 smn[8], smx[8];
    int b = blockIdx.x >> 4;
    int chunk = blockIdx.x & 15;
    int tid = threadIdx.x, lane = tid & 31;
    for (int j = tid; j < 256 * 68 / 4; j += 256) ((u32*)sc)[j] = 0;
    float th = rt[b];
    float thA = (th == 0.0f) ? 1.0f : ((th == 255.0f) ? 254.0f : th);
    u32 mn = 0xFFFFFFFFu, mx = 0u;
    const float4* xb4 = (const float4*)(x + (size_t)b * HWN);
    u32* bm = (u32*)g_pre[b];
    int base = chunk * 4096;
    __syncthreads();
    float4 xv = xb4[base + tid];
    for (int it = 0; it < 16; it++) {
        int gf4 = base + it * 256 + tid;
        float4 nx;
        if (it < 15) nx = xb4[gf4 + 256];
        float e[4] = {xv.x, xv.y, xv.z, xv.w};
        u32 nib = 0;
#pragma unroll
        for (int k = 0; k < 4; k++) {
            float cam = e[k];
            u32 cb2 = __float_as_uint(cam);
            mn = min(mn, cb2); mx = max(mx, cb2);
            sc[tid * 68 + cbin(cam + 1e-8f)]++;
            if (floorf(cam * 255.0f) > thA) nib |= (1u << k);
        }
        u32 vv = nib << (4 * (lane & 7));
        vv |= __shfl_xor_sync(0xFFFFFFFFu, vv, 1);
        vv |= __shfl_xor_sync(0xFFFFFFFFu, vv, 2);
        vv |= __shfl_xor_sync(0xFFFFFFFFu, vv, 4);
        if ((lane & 7) == 0) bm[gf4 >> 3] = vv;
        xv = nx;
    }
    __syncthreads();
    if (tid < 64) {
        u32 s = 0;
        for (int t2 = 0; t2 < 256; t2++) s += sc[t2 * 68 + tid];
        if (s) atomicAdd(&g_ch_all[b][tid], s);
    }
    for (int o = 16; o; o >>= 1) {
        mn = min(mn, __shfl_down_sync(0xFFFFFFFFu, mn, o));
        mx = max(mx, __shfl_down_sync(0xFFFFFFFFu, mx, o));
    }
    if (lane == 0) { smn[tid >> 5] = mn; smx[tid >> 5] = mx; }
    __syncthreads();
    if (tid == 0) {
        for (int w = 1; w < 8; w++) { mn = min(mn, smn[w]); mx = max(mx, smx[w]); }
        atomicMin(&g_minb[b], mn);
        atomicMax(&g_maxb[b], mx);
        __threadfence();
        int d = atomicAdd(&g_done1[b], 1);
        if (d == 15) {
            u32 mnv = atomicMin(&g_minb[b], 0xFFFFFFFFu);
            u32 mxv = atomicMax(&g_maxb[b], 0u);
            g_deg[b] = (mnv == mxv) ? 1 : 0;
            int cum = 0, Bb = 64, nd = 0;
            for (int j = 0; j < 64; j++) {
                int c = (int)atomicAdd(&g_ch_all[b][j], 0u);
                if (cum + c >= NBGC) { Bb = j; nd = NBGC - cum; break; }
                cum += c;
            }
            g_BbC[b] = Bb; g_needB[b] = nd;
        }
    }
}

// P2: 11x11 erosion + roi popcount -> n_fg, FUSED roi 64-bin hist + fg scan
__global__ void __launch_bounds__(1024) k_erode(const float* __restrict__ x) {
    extern __shared__ ull dsm[];
    ull* s_pre = dsm;                    // 4096 ull (reused: final roi)
    ull* s_hb  = dsm + 4096;             // 4096 ull
    u8*  sc    = (u8*)(dsm + 8192);      // 1024*68 bytes
    __shared__ int red[32];
    __shared__ int s_nfg;
    __shared__ u32 bh[64];
    int b = blockIdx.x, tid = threadIdx.x, lane = tid & 31;
    for (int i = tid; i < 4096; i += 1024) s_pre[i] = g_pre[b][i];
    __syncthreads();
    for (int i = tid; i < 4096; i += 1024) {
        int w = i & 7;
        ull av = s_pre[i];
        ull lo = w ? s_pre[i - 1] : ~0ull;
        ull hi = (w < 7) ? s_pre[i + 1] : ~0ull;
        ull r = av;
#pragma unroll
        for (int d = 1; d <= 5; d++)
            r &= ((av >> d) | (hi << (64 - d))) & ((av << d) | (lo >> (64 - d)));
        s_hb[i] = r;
    }
    __syncthreads();
    int pc = 0;
    for (int i = tid; i < 4096; i += 1024) {
        int row = i >> 3, w = i & 7;
        ull r = ~0ull;
#pragma unroll
        for (int d = -5; d <= 5; d++) {
            int rr = row + d;
            if (rr >= 0 && rr < HN) r &= s_hb[rr * 8 + w];
        }
        g_er[b][i] = r;
        s_pre[i] = r;     // keep roi in smem for hist phase
        pc += __popcll(r);
    }
    for (int o = 16; o; o >>= 1) pc += __shfl_down_sync(0xFFFFFFFFu, pc, o);
    if (lane == 0) red[tid >> 5] = pc;
    __syncthreads();
    if (tid == 0) {
        int c = 0;
        for (int w = 0; w < 32; w++) c += red[w];
        int nfg = (int)floorf(0.3f * (float)c);
        g_nfg[b] = nfg;
        s_nfg = nfg;
    }
    __syncthreads();
    int nfg = s_nfg;
    if (nfg > 0) {
        for (int j = tid * 17; j < tid * 17 + 17; j++) ((u32*)sc)[j] = 0;
        __syncthreads();
        const float4* xb4 = (const float4*)(x + (size_t)b * HWN);
        for (int it = 0; it < 64; it++) {
            int gf4 = it * 1024 + tid;
            int p = gf4 * 4;
            u32 bits4 = (u32)(s_pre[(p >> 9) * 8 + ((p & 511) >> 6)] >> (p & 63)) & 0xFu;
            if (bits4) {
                float4 xv = xb4[gf4];
                if (bits4 & 1u) sc[tid * 68 + cbin(xv.x + 1e-8f)]++;
                if (bits4 & 2u) sc[tid * 68 + cbin(xv.y + 1e-8f)]++;
                if (bits4 & 4u) sc[tid * 68 + cbin(xv.z + 1e-8f)]++;
                if (bits4 & 8u) sc[tid * 68 + cbin(xv.w + 1e-8f)]++;
            }
        }
        __syncthreads();
        if (tid < 64) {
            u32 s = 0;
            for (int t2 = 0; t2 < 1024; t2++) s += sc[t2 * 68 + tid];
            bh[tid] = s;
        }
        __syncthreads();
    }
    if (tid == 0) {
        int Bf = 64, nd = 0;
        if (nfg > 0) {
            int cum = 0;
            for (int j = 63; j >= 0; j--) {
                int c = (int)bh[j];
                if (cum + c >= nfg) { Bf = j; nd = nfg - cum; break; }
                cum += c;
            }
        }
        g_BfC[b] = Bf; g_needF[b] = nd;
    }
}

// P3: streaming classify — coalesced, software-pipelined loads; emit records.
__global__ void __launch_bounds__(256) k_score(const float* __restrict__ x,
                                               const float* __restrict__ ufg,
                                               const float* __restrict__ ubg) {
    int b = blockIdx.x >> 4;
    int chunk = blockIdx.x & 15;
    int tid = threadIdx.x, lane = tid & 31;
    int BbC = g_BbC[b], BfC = g_BfC[b];
    const float4* xb4 = (const float4*)(x + (size_t)b * HWN);
    const float4* uf4 = (const float4*)(ufg + (size_t)b * HWN);
    const float4* ub4 = (const float4*)(ubg + (size_t)b * HWN);
    const u32* erw = (const u32*)g_er[b];
    int base = chunk * 4096;
    u32 lt = (1u << lane) - 1u;
    float4 xv = xb4[base + tid];
    float4 ufv = uf4[base + tid];
    float4 ubv = ub4[base + tid];
    for (int it = 0; it < 16; it++) {
        int gf4 = base + it * 256 + tid;
        float4 nx, nf, nb2;
        if (it < 15) {
            nx = xb4[gf4 + 256];
            nf = uf4[gf4 + 256];
            nb2 = ub4[gf4 + 256];
        }
        u32 rbits = (erw[gf4 >> 3] >> ((gf4 & 7) * 4)) & 0xFu;
        float vx[4] = {xv.x + 1e-8f, xv.y + 1e-8f, xv.z + 1e-8f, xv.w + 1e-8f};
        float euf[4] = {ufv.x, ufv.y, ufv.z, ufv.w};
        float eub[4] = {ubv.x, ubv.y, ubv.z, ubv.w};
        bool bs[4], bb[4], fs[4], fb[4];
        ull recB[4], recF[4], keyB[4], keyF[4];
#pragma unroll
        for (int k = 0; k < 4; k++) {
            float v = vx[k];
            int c = cbin(v);
            int pix = gf4 * 4 + k;
            int roi = (rbits >> k) & 1;
            bs[k] = c < BbC;  bb[k] = (c == BbC);
            fs[k] = roi && (c > BfC);  fb[k] = roi && (c == BfC);
            recB[k] = (((ull)(__float_as_uint(eub[k]) | 0x80000000u)) << 32) | (u32)pix;
            recF[k] = (((ull)(__float_as_uint(euf[k]) | 0x80000000u)) << 32) | (u32)pix;
            u32 vb = __float_as_uint(v);
            keyB[k] = ~((((ull)vb) << 32) | (u32)pix);
            keyF[k] = (((ull)vb) << 32) | (u32)(HWN - 1 - pix);
        }
        {   // sure bg records
            u32 m0 = __ballot_sync(~0u, bs[0]), m1 = __ballot_sync(~0u, bs[1]);
            u32 m2 = __ballot_sync(~0u, bs[2]), m3 = __ballot_sync(~0u, bs[3]);
            int p0 = __popc(m0), p01 = p0 + __popc(m1), p012 = p01 + __popc(m2);
            int tot = p012 + __popc(m3);
            int bse = 0;
            if (lane == 0 && tot) bse = atomicAdd(&g_n[1][b], tot);
            bse = __shfl_sync(~0u, bse, 0);
            if (bs[0]) { int j = bse + __popc(m0 & lt);        if (j < CAPC) g_rec[1][b][j] = recB[0]; }
            if (bs[1]) { int j = bse + p0 + __popc(m1 & lt);   if (j < CAPC) g_rec[1][b][j] = recB[1]; }
            if (bs[2]) { int j = bse + p01 + __popc(m2 & lt);  if (j < CAPC) g_rec[1][b][j] = recB[2]; }
            if (bs[3]) { int j = bse + p012 + __popc(m3 & lt); if (j < CAPC) g_rec[1][b][j] = recB[3]; }
        }
        {   // sure fg records
            u32 m0 = __ballot_sync(~0u, fs[0]), m1 = __ballot_sync(~0u, fs[1]);
            u32 m2 = __ballot_sync(~0u, fs[2]), m3 = __ballot_sync(~0u, fs[3]);
            int p0 = __popc(m0), p01 = p0 + __popc(m1), p012 = p01 + __popc(m2);
            int tot = p012 + __popc(m3);
            int bse = 0;
            if (lane == 0 && tot) bse = atomicAdd(&g_n[0][b], tot);
            bse = __shfl_sync(~0u, bse, 0);
            if (fs[0]) { int j = bse + __popc(m0 & lt);        if (j < CAPC) g_rec[0][b][j] = recF[0]; }
            if (fs[1]) { int j = bse + p0 + __popc(m1 & lt);   if (j < CAPC) g_rec[0][b][j] = recF[1]; }
            if (fs[2]) { int j = bse + p01 + __popc(m2 & lt);  if (j < CAPC) g_rec[0][b][j] = recF[2]; }
            if (fs[3]) { int j = bse + p012 + __popc(m3 & lt); if (j < CAPC) g_rec[0][b][j] = recF[3]; }
        }
        {   // bg boundary pairs
            u32 m0 = __ballot_sync(~0u, bb[0]), m1 = __ballot_sync(~0u, bb[1]);
            u32 m2 = __ballot_sync(~0u, bb[2]), m3 = __ballot_sync(~0u, bb[3]);
            int p0 = __popc(m0), p01 = p0 + __popc(m1), p012 = p01 + __popc(m2);
            int tot = p012 + __popc(m3);
            int bse = 0;
            if (lane == 0 && tot) bse = atomicAdd(&g_np[1][b], tot);
            bse = __shfl_sync(~0u, bse, 0);
            if (bb[0]) { int j = bse + __popc(m0 & lt);        if (j < CAPP) { g_p1[1][b][j] = keyB[0]; g_pr[1][b][j] = recB[0]; } }
            if (bb[1]) { int j = bse + p0 + __popc(m1 & lt);   if (j < CAPP) { g_p1[1][b][j] = keyB[1]; g_pr[1][b][j] = recB[1]; } }
            if (bb[2]) { int j = bse + p01 + __popc(m2 & lt);  if (j < CAPP) { g_p1[1][b][j] = keyB[2]; g_pr[1][b][j] = recB[2]; } }
            if (bb[3]) { int j = bse + p012 + __popc(m3 & lt); if (j < CAPP) { g_p1[1][b][j] = keyB[3]; g_pr[1][b][j] = recB[3]; } }
        }
        {   // fg boundary pairs
            u32 m0 = __ballot_sync(~0u, fb[0]), m1 = __ballot_sync(~0u, fb[1]);
            u32 m2 = __ballot_sync(~0u, fb[2]), m3 = __ballot_sync(~0u, fb[3]);
            int p0 = __popc(m0), p01 = p0 + __popc(m1), p012 = p01 + __popc(m2);
            int tot = p012 + __popc(m3);
            int bse = 0;
            if (lane == 0 && tot) bse = atomicAdd(&g_np[0][b], tot);
            bse = __shfl_sync(~0u, bse, 0);
            if (fb[0]) { int j = bse + __popc(m0 & lt);        if (j < CAPP) { g_p1[0][b][j] = keyF[0]; g_pr[0][b][j] = recF[0]; } }
            if (fb[1]) { int j = bse + p0 + __popc(m1 & lt);   if (j < CAPP) { g_p1[0][b][j] = keyF[1]; g_pr[0][b][j] = recF[1]; } }
            if (fb[2]) { int j = bse + p01 + __popc(m2 & lt);  if (j < CAPP) { g_p1[0][b][j] = keyF[2]; g_pr[0][b][j] = recF[2]; } }
            if (fb[3]) { int j = bse + p012 + __popc(m3 & lt); if (j < CAPP) { g_p1[0][b][j] = keyF[3]; g_pr[0][b][j] = recF[3]; } }
        }
        xv = nx; ufv = nf; ubv = nb2;
    }
}

// P4: stage-1 refine (inline) + sparse exact top-K with u-tier verification
__global__ void __launch_bounds__(1024) k_topk(const float* __restrict__ x) {
    __shared__ int s_cnt;
    __shared__ int s_done;
    int b = blockIdx.x, side = blockIdx.y;
    int K;
    if (side == 0) {
        int nf = g_nfg[b];
        K = g_deg[b] ? 0 : (nf < 100 ? nf : 100);
    } else {
        K = g_deg[b] ? 0 : 100;
    }
    if (K <= 0) return;
    int N = g_n[side][b];
    if (N > CAPC) N = CAPC;
    int need = side ? g_needB[b] : g_needF[b];
    int np = 0;
    ull Tv = 0;
    if (need > 0) {
        np = g_np[side][b];
        if (np > CAPP) np = CAPP;
        Tv = radix_kth_largest(g_p1[side][b], np, need);
    }
    const ull* recs = g_rec[side][b];
    const ull* bkeys = g_p1[side][b];
    const ull* brecs = g_pr[side][b];
    ull* sk = g_sk[side][b];
    const float* xb = x + (size_t)b * HWN;
    int tid = threadIdx.x;
    if (tid == 0) s_done = 0;
    __syncthreads();
    for (int tier = 0; tier < 3; tier++) {
        if (s_done) break;
        u32 ucut = (tier == 0) ? UCUT0 : (tier == 1) ? UCUT1 : 0u;
        if (tid == 0) s_cnt = 0;
        __syncthreads();
        int tot = N + np;
        for (int i = tid; i < tot; i += 1024) {
            ull r;
            if (i < N) r = recs[i];
            else {
                if (bkeys[i - N] < Tv) continue;
                r = brecs[i - N];
            }
            u32 uhi = (u32)(r >> 32);
            if (uhi >= ucut) {
                float u = __uint_as_float(uhi & 0x7FFFFFFFu);
                int pix = (int)(r & 0xFFFFFFFFull);
                float v = xb[pix] + 1e-8f;
                float p = side ? (fmaxf(1.0f - v, 0.0f) + 1e-8f) : v;
                float s = logf(p) - logf(-logf(u));
                int pos = atomicAdd(&s_cnt, 1);
                sk[pos] = (((ull)fmono(s)) << 32) | (u32)(HWN - 1 - pix);
            }
        }
        __syncthreads();
        int cnt = s_cnt;
        bool ok = false;
        ull T = 0;
        if (cnt >= K) {
            T = radix_kth_largest(sk, cnt, K);
            if (tier == 2) ok = true;
            else {
                float sK = fmono_inv((u32)(T >> 32));
                float edge = (tier == 0) ? 0.984375f : 0.75f;
                float gc = -logf(-logf(edge));
                ok = (sK > gc);   // excluded s <= g <= gc < sK
            }
        }
        if (ok) {
            ull* seed = g_seed[side][b];
            for (int i = tid; i < cnt; i += 1024)
                if (sk[i] >= T) mark_seed(seed, HWN - 1 - (int)(sk[i] & 0xFFFFFFFFull));
            if (tid == 0) s_done = 1;
        }
        __syncthreads();
    }
}

// P5: 3x3 dilation + compose; 16-row bands, float4 stores
__global__ void __launch_bounds__(256) k_output(float* __restrict__ out) {
    __shared__ ull sv[2][16][8], sh[2][16][8];
    int b = blockIdx.x >> 5, band = blockIdx.x & 31, r0 = band * 16;
    int t = threadIdx.x;
    {
        int side = t >> 7, rr = (t >> 3) & 15, w = t & 7;
        int r = r0 + rr;
        const ull* sd = g_seed[side][b];
        ull v = sd[r * 8 + w];
        if (r > 0)   v |= sd[(r - 1) * 8 + w];
        if (r < 511) v |= sd[(r + 1) * 8 + w];
        sv[side][rr][w] = v;
    }
    __syncthreads();
    {
        int side = t >> 7, rr = (t >> 3) & 15, w = t & 7;
        ull m = sv[side][rr][w];
        ull h = m | (m << 1) | (m >> 1);
        if (w > 0) h |= sv[side][rr][w - 1] >> 63;
        if (w < 7) h |= sv[side][rr][w + 1] << 63;
        sh[side][rr][w] = h;
    }
    __syncthreads();
    int rr = t >> 4, c0 = (t & 15) * 32;
    int w = c0 >> 6, half = c0 & 32;
    u32 fb = (u32)(sh[0][rr][w] >> half);
    u32 gb = (u32)(sh[1][rr][w] >> half);
    float4* o4 = (float4*)(out + (size_t)b * HWN + (size_t)(r0 + rr) * WN + c0);
#pragma unroll
    for (int j = 0; j < 8; j++) {
        float vv[4];
#pragma unroll
        for (int k = 0; k < 4; k++) {
            int bit = j * 4 + k;
            int f = (fb >> bit) & 1, g = (gb >> bit) & 1;
            vv[k] = (f && !g) ? 1.0f : ((g && !f) ? 0.0f : -255.0f);
        }
        o4[j] = make_float4(vv[0], vv[1], vv[2], vv[3]);
    }
}

extern "C" void kernel_launch(void* const* d_in, const int* in_sizes, int n_in,
                              void* d_out, int out_size) {
    (void)out_size;
    const float* big[3] = {nullptr, nullptr, nullptr};
    const float* rt = nullptr;
    int nb = 0;
    for (int i = 0; i < n_in && i < 4; i++) {
        if (in_sizes[i] == BN) rt = (const float*)d_in[i];
        else if (nb < 3)       big[nb++] = (const float*)d_in[i];
    }
    const float* x   = big[0];
    const float* ufg = big[1];
    const float* ubg = big[2];
    float* out = (float*)d_out;

    const int ERODE_SMEM = 8192 * 8 + 1024 * 68;   // 65536 + 69632 = 135168
    cudaFuncSetAttribute(k_erode, cudaFuncAttributeMaxDynamicSharedMemorySize, ERODE_SMEM);

    k_zero<<<512, 256>>>();
    k_prep<<<BN * 16, 256>>>(x, rt);
    k_erode<<<BN, 1024, ERODE_SMEM>>>(x);
    k_score<<<BN * 16, 256>>>(x, ufg, ubg);
    k_topk<<<dim3(BN, 2), 1024>>>(x);
    k_output<<<2048, 256>>>(out);
}

// round 16
// speedup vs baseline: 2.2927x; 1.0352x over previous
#include <cuda_runtime.h>
#include <cuda_bf16.h>
#include <math.h>

#define BN    64
#define HN    512
#define WN    512
#define HWN   262144
#define NBGC  78643
#define CAPP  16384
#define CAPC  79872

#define UCUT0 0xBF7C0000u   // fmono(0.984375f)
#define UCUT1 0xBF400000u   // fmono(0.75f)

typedef unsigned long long ull;
typedef unsigned int       u32;
typedef unsigned char      u8;

__device__ ull g_pre[BN][HN * 8];
__device__ ull g_er [BN][HN * 8];
__device__ u32 g_bin8[BN][HWN / 4];   // packed 4x u8 bins per u32
__device__ u32 g_ch_all[BN][64];
__device__ u32 g_minb[BN], g_maxb[BN];
__device__ int g_nfg[BN], g_deg[BN];
__device__ int g_BbC[BN], g_needB[BN];
__device__ int g_BfC[BN], g_needF[BN];
__device__ int g_done1[BN];
__device__ ull g_rec[2][BN][CAPC];    // sure candidate records (ubits|msb)<<32|pix
__device__ int g_n[2][BN];
__device__ ull g_pr[2][BN][CAPP];     // boundary records
__device__ int g_np[2][BN];
__device__ ull g_p1[2][BN][CAPP];     // boundary value keys (built in topk)
__device__ ull g_sk[2][BN][CAPC];     // score-key scratch
__device__ ull g_seed[2][BN][HN * 8];

__device__ __forceinline__ int cbin(float v) {
    int k = (int)(v * 64.0f);
    return k > 63 ? 63 : k;
}
__device__ __forceinline__ u32 fmono(float f) {
    u32 b = __float_as_uint(f);
    return (b & 0x80000000u) ? ~b : (b | 0x80000000u);
}
__device__ __forceinline__ float fmono_inv(u32 m) {
    u32 b = (m & 0x80000000u) ? (m ^ 0x80000000u) : ~m;
    return __uint_as_float(b);
}
__device__ __forceinline__ void mark_seed(ull* seedimg, int pix) {
    atomicOr(&seedimg[(pix >> 9) * 8 + ((pix & 511) >> 6)], 1ull << (pix & 63));
}

__device__ __forceinline__ ull radix_kth_largest(const ull* __restrict__ list,
                                                 int cnt, int need) {
    __shared__ u32 rh[256];
    __shared__ ull s_pref;
    __shared__ int s_nd;
    int tid = threadIdx.x;
    if (tid == 0) { s_pref = 0ull; s_nd = need; }
    __syncthreads();
    for (int by = 7; by >= 0; --by) {
        for (int j = tid; j < 256; j += blockDim.x) rh[j] = 0;
        __syncthreads();
        ull mask = (by == 7) ? 0ull : (~0ull << (8 * (by + 1)));
        ull pref = s_pref;
        for (int i = tid; i < cnt; i += blockDim.x) {
            ull k = list[i];
            if (((k ^ pref) & mask) == 0ull)
                atomicAdd(&rh[(int)((k >> (8 * by)) & 255ull)], 1u);
        }
        __syncthreads();
        if (tid == 0) {
            int nd = s_nd; int cum = 0; int sel = 0;
            for (int v = 255; v >= 0; --v) {
                u32 c = rh[v];
                if (cum + (int)c >= nd) { sel = v; s_nd = nd - cum; break; }
                cum += c;
            }
            s_pref = pref | (((ull)sel) << (8 * by));
        }
        __syncthreads();
    }
    return s_pref;
}

__global__ void k_zero() {
    int i = blockIdx.x * blockDim.x + threadIdx.x;
    int stride = gridDim.x * blockDim.x;
    ull* seeds = &g_seed[0][0][0];
    for (int j = i; j < 2 * BN * HN * 8; j += stride) seeds[j] = 0ull;
    u32* h1 = &g_ch_all[0][0];
    for (int j = i; j < BN * 64; j += stride) h1[j] = 0;
    if (i < BN) {
        g_n[0][i] = 0;  g_n[1][i] = 0;
        g_np[0][i] = 0; g_np[1][i] = 0;
        g_done1[i] = 0;
        g_minb[i] = 0xFFFFFFFFu; g_maxb[i] = 0u;
    }
}

// P1: x -> pre-erosion bitmap, minmax, 64-bin hist, packed bin array
__global__ void __launch_bounds__(256) k_prep(const float* __restrict__ x,
                                              const float* __restrict__ rt) {
    __shared__ u8 sc[256 * 68];
    __shared__ u32 smn[8], smx[8];
    int b = blockIdx.x >> 4;
    int chunk = blockIdx.x & 15;
    int tid = threadIdx.x, lane = tid & 31;
    for (int j = tid; j < 256 * 68 / 4; j += 256) ((u32*)sc)[j] = 0;
    float th = rt[b];
    float thA = (th == 0.0f) ? 1.0f : ((th == 255.0f) ? 254.0f : th);
    u32 mn = 0xFFFFFFFFu, mx = 0u;
    const float4* xb4 = (const float4*)(x + (size_t)b * HWN);
    u32* bm = (u32*)g_pre[b];
    u32* binw = g_bin8[b];
    int base = chunk * 4096;
    __syncthreads();
    float4 xv = xb4[base + tid];
    for (int it = 0; it < 16; it++) {
        int gf4 = base + it * 256 + tid;
        float4 nx;
        if (it < 15) nx = xb4[gf4 + 256];
        float e[4] = {xv.x, xv.y, xv.z, xv.w};
        u32 nib = 0, packed = 0;
#pragma unroll
        for (int k = 0; k < 4; k++) {
            float cam = e[k];
            u32 cb2 = __float_as_uint(cam);
            mn = min(mn, cb2); mx = max(mx, cb2);
            int bin = cbin(__fadd_rn(cam, 1e-8f));
            sc[tid * 68 + bin]++;
            packed |= ((u32)bin) << (8 * k);
            if (floorf(cam * 255.0f) > thA) nib |= (1u << k);
        }
        binw[gf4] = packed;
        u32 vv = nib << (4 * (lane & 7));
        vv |= __shfl_xor_sync(0xFFFFFFFFu, vv, 1);
        vv |= __shfl_xor_sync(0xFFFFFFFFu, vv, 2);
        vv |= __shfl_xor_sync(0xFFFFFFFFu, vv, 4);
        if ((lane & 7) == 0) bm[gf4 >> 3] = vv;
        xv = nx;
    }
    __syncthreads();
    if (tid < 64) {
        u32 s = 0;
        for (int t2 = 0; t2 < 256; t2++) s += sc[t2 * 68 + tid];
        if (s) atomicAdd(&g_ch_all[b][tid], s);
    }
    for (int o = 16; o; o >>= 1) {
        mn = min(mn, __shfl_down_sync(0xFFFFFFFFu, mn, o));
        mx = max(mx, __shfl_down_sync(0xFFFFFFFFu, mx, o));
    }
    if (lane == 0) { smn[tid >> 5] = mn; smx[tid >> 5] = mx; }
    __syncthreads();
    if (tid == 0) {
        for (int w = 1; w < 8; w++) { mn = min(mn, smn[w]); mx = max(mx, smx[w]); }
        atomicMin(&g_minb[b], mn);
        atomicMax(&g_maxb[b], mx);
        __threadfence();
        int d = atomicAdd(&g_done1[b], 1);
        if (d == 15) {
            u32 mnv = atomicMin(&g_minb[b], 0xFFFFFFFFu);
            u32 mxv = atomicMax(&g_maxb[b], 0u);
            g_deg[b] = (mnv == mxv) ? 1 : 0;
            int cum = 0, Bb = 64, nd = 0;
            for (int j = 0; j < 64; j++) {
                int c = (int)atomicAdd(&g_ch_all[b][j], 0u);
                if (cum + c >= NBGC) { Bb = j; nd = NBGC - cum; break; }
                cum += c;
            }
            g_BbC[b] = Bb; g_needB[b] = nd;
        }
    }
}

// P2: 11x11 erosion + roi popcount -> n_fg; fused roi hist + fg coarse scan
__global__ void __launch_bounds__(1024) k_erode(const float* __restrict__ x) {
    extern __shared__ ull dsm[];
    ull* s_pre = dsm;
    ull* s_hb  = dsm + 4096;
    u8*  sc    = (u8*)(dsm + 8192);
    __shared__ int red[32];
    __shared__ int s_nfg;
    __shared__ u32 bh[64];
    int b = blockIdx.x, tid = threadIdx.x, lane = tid & 31;
    for (int i = tid; i < 4096; i += 1024) s_pre[i] = g_pre[b][i];
    __syncthreads();
    for (int i = tid; i < 4096; i += 1024) {
        int w = i & 7;
        ull av = s_pre[i];
        ull lo = w ? s_pre[i - 1] : ~0ull;
        ull hi = (w < 7) ? s_pre[i + 1] : ~0ull;
        ull r = av;
#pragma unroll
        for (int d = 1; d <= 5; d++)
            r &= ((av >> d) | (hi << (64 - d))) & ((av << d) | (lo >> (64 - d)));
        s_hb[i] = r;
    }
    __syncthreads();
    int pc = 0;
    for (int i = tid; i < 4096; i += 1024) {
        int row = i >> 3, w = i & 7;
        ull r = ~0ull;
#pragma unroll
        for (int d = -5; d <= 5; d++) {
            int rr = row + d;
            if (rr >= 0 && rr < HN) r &= s_hb[rr * 8 + w];
        }
        g_er[b][i] = r;
        s_pre[i] = r;
        pc += __popcll(r);
    }
    for (int o = 16; o; o >>= 1) pc += __shfl_down_sync(0xFFFFFFFFu, pc, o);
    if (lane == 0) red[tid >> 5] = pc;
    __syncthreads();
    if (tid == 0) {
        int c = 0;
        for (int w = 0; w < 32; w++) c += red[w];
        int nfg = (int)floorf(0.3f * (float)c);
        g_nfg[b] = nfg;
        s_nfg = nfg;
    }
    __syncthreads();
    int nfg = s_nfg;
    if (nfg > 0) {
        for (int j = tid * 17; j < tid * 17 + 17; j++) ((u32*)sc)[j] = 0;
        __syncthreads();
        const u32* binw = g_bin8[b];
        for (int it = 0; it < 64; it++) {
            int gf4 = it * 1024 + tid;
            int p = gf4 * 4;
            u32 bits4 = (u32)(s_pre[(p >> 9) * 8 + ((p & 511) >> 6)] >> (p & 63)) & 0xFu;
            if (bits4) {
                u32 pk = binw[gf4];
                if (bits4 & 1u) sc[tid * 68 + (pk & 63u)]++;
                if (bits4 & 2u) sc[tid * 68 + ((pk >> 8) & 63u)]++;
                if (bits4 & 4u) sc[tid * 68 + ((pk >> 16) & 63u)]++;
                if (bits4 & 8u) sc[tid * 68 + ((pk >> 24) & 63u)]++;
            }
        }
        __syncthreads();
        if (tid < 64) {
            u32 s = 0;
            for (int t2 = 0; t2 < 1024; t2++) s += sc[t2 * 68 + tid];
            bh[tid] = s;
        }
        __syncthreads();
    }
    if (tid == 0) {
        int Bf = 64, nd = 0;
        if (nfg > 0) {
            int cum = 0;
            for (int j = 63; j >= 0; j--) {
                int c = (int)bh[j];
                if (cum + c >= nfg) { Bf = j; nd = nfg - cum; break; }
                cum += c;
            }
        }
        g_BfC[b] = Bf; g_needF[b] = nd;
    }
}

// P3: streaming classify from bins + u; x never touched.
__global__ void __launch_bounds__(256) k_score(const float* __restrict__ ufg,
                                               const float* __restrict__ ubg) {
    int b = blockIdx.x >> 4;
    int chunk = blockIdx.x & 15;
    int tid = threadIdx.x, lane = tid & 31;
    int BbC = g_BbC[b], BfC = g_BfC[b];
    bool doFg = g_nfg[b] > 0;
    const u32* binw = g_bin8[b];
    const float4* uf4 = (const float4*)(ufg + (size_t)b * HWN);
    const float4* ub4 = (const float4*)(ubg + (size_t)b * HWN);
    const u32* erw = (const u32*)g_er[b];
    int base = chunk * 4096;
    u32 lt = (1u << lane) - 1u;
    u32 pk = binw[base + tid];
    float4 ubv = ub4[base + tid];
    float4 ufv;
    if (doFg) ufv = uf4[base + tid];
    for (int it = 0; it < 16; it++) {
        int gf4 = base + it * 256 + tid;
        u32 npk = 0; float4 nb2, nf;
        if (it < 15) {
            npk = binw[gf4 + 256];
            nb2 = ub4[gf4 + 256];
            if (doFg) nf = uf4[gf4 + 256];
        }
        float eub[4] = {ubv.x, ubv.y, ubv.z, ubv.w};
        int bin[4] = {(int)(pk & 63u), (int)((pk >> 8) & 63u),
                      (int)((pk >> 16) & 63u), (int)((pk >> 24) & 63u)};
        bool bs[4], bb[4];
        ull recB[4];
#pragma unroll
        for (int k = 0; k < 4; k++) {
            int pix = gf4 * 4 + k;
            bs[k] = bin[k] < BbC;  bb[k] = (bin[k] == BbC);
            recB[k] = (((ull)(__float_as_uint(eub[k]) | 0x80000000u)) << 32) | (u32)pix;
        }
        {   // sure bg
            u32 m0 = __ballot_sync(~0u, bs[0]), m1 = __ballot_sync(~0u, bs[1]);
            u32 m2 = __ballot_sync(~0u, bs[2]), m3 = __ballot_sync(~0u, bs[3]);
            int p0 = __popc(m0), p01 = p0 + __popc(m1), p012 = p01 + __popc(m2);
            int tot = p012 + __popc(m3);
            int bse = 0;
            if (lane == 0 && tot) bse = atomicAdd(&g_n[1][b], tot);
            bse = __shfl_sync(~0u, bse, 0);
            if (bs[0]) { int j = bse + __popc(m0 & lt);        if (j < CAPC) g_rec[1][b][j] = recB[0]; }
            if (bs[1]) { int j = bse + p0 + __popc(m1 & lt);   if (j < CAPC) g_rec[1][b][j] = recB[1]; }
            if (bs[2]) { int j = bse + p01 + __popc(m2 & lt);  if (j < CAPC) g_rec[1][b][j] = recB[2]; }
            if (bs[3]) { int j = bse + p012 + __popc(m3 & lt); if (j < CAPC) g_rec[1][b][j] = recB[3]; }
        }
        {   // bg boundary records
            u32 m0 = __ballot_sync(~0u, bb[0]), m1 = __ballot_sync(~0u, bb[1]);
            u32 m2 = __ballot_sync(~0u, bb[2]), m3 = __ballot_sync(~0u, bb[3]);
            int p0 = __popc(m0), p01 = p0 + __popc(m1), p012 = p01 + __popc(m2);
            int tot = p012 + __popc(m3);
            int bse = 0;
            if (lane == 0 && tot) bse = atomicAdd(&g_np[1][b], tot);
            bse = __shfl_sync(~0u, bse, 0);
            if (bb[0]) { int j = bse + __popc(m0 & lt);        if (j < CAPP) g_pr[1][b][j] = recB[0]; }
            if (bb[1]) { int j = bse + p0 + __popc(m1 & lt);   if (j < CAPP) g_pr[1][b][j] = recB[1]; }
            if (bb[2]) { int j = bse + p01 + __popc(m2 & lt);  if (j < CAPP) g_pr[1][b][j] = recB[2]; }
            if (bb[3]) { int j = bse + p012 + __popc(m3 & lt); if (j < CAPP) g_pr[1][b][j] = recB[3]; }
        }
        if (doFg) {
            u32 rbits = (erw[gf4 >> 3] >> ((gf4 & 7) * 4)) & 0xFu;
            float euf[4] = {ufv.x, ufv.y, ufv.z, ufv.w};
            bool fs[4], fb[4];
            ull recF[4];
#pragma unroll
            for (int k = 0; k < 4; k++) {
                int pix = gf4 * 4 + k;
                int roi = (rbits >> k) & 1;
                fs[k] = roi && (bin[k] > BfC);
                fb[k] = roi && (bin[k] == BfC);
                recF[k] = (((ull)(__float_as_uint(euf[k]) | 0x80000000u)) << 32) | (u32)pix;
            }
            {
                u32 m0 = __ballot_sync(~0u, fs[0]), m1 = __ballot_sync(~0u, fs[1]);
                u32 m2 = __ballot_sync(~0u, fs[2]), m3 = __ballot_sync(~0u, fs[3]);
                int p0 = __popc(m0), p01 = p0 + __popc(m1), p012 = p01 + __popc(m2);
                int tot = p012 + __popc(m3);
                int bse = 0;
                if (lane == 0 && tot) bse = atomicAdd(&g_n[0][b], tot);
                bse = __shfl_sync(~0u, bse, 0);
                if (fs[0]) { int j = bse + __popc(m0 & lt);        if (j < CAPC) g_rec[0][b][j] = recF[0]; }
                if (fs[1]) { int j = bse + p0 + __popc(m1 & lt);   if (j < CAPC) g_rec[0][b][j] = recF[1]; }
                if (fs[2]) { int j = bse + p01 + __popc(m2 & lt);  if (j < CAPC) g_rec[0][b][j] = recF[2]; }
                if (fs[3]) { int j = bse + p012 + __popc(m3 & lt); if (j < CAPC) g_rec[0][b][j] = recF[3]; }
            }
            {
                u32 m0 = __ballot_sync(~0u, fb[0]), m1 = __ballot_sync(~0u, fb[1]);
                u32 m2 = __ballot_sync(~0u, fb[2]), m3 = __ballot_sync(~0u, fb[3]);
                int p0 = __popc(m0), p01 = p0 + __popc(m1), p012 = p01 + __popc(m2);
                int tot = p012 + __popc(m3);
                int bse = 0;
                if (lane == 0 && tot) bse = atomicAdd(&g_np[0][b], tot);
                bse = __shfl_sync(~0u, bse, 0);
                if (fb[0]) { int j = bse + __popc(m0 & lt);        if (j < CAPP) g_pr[0][b][j] = recF[0]; }
                if (fb[1]) { int j = bse + p0 + __popc(m1 & lt);   if (j < CAPP) g_pr[0][b][j] = recF[1]; }
                if (fb[2]) { int j = bse + p01 + __popc(m2 & lt);  if (j < CAPP) g_pr[0][b][j] = recF[2]; }
                if (fb[3]) { int j = bse + p012 + __popc(m3 & lt); if (j < CAPP) g_pr[0][b][j] = recF[3]; }
            }
            ufv = nf;
        }
        pk = npk; ubv = nb2;
    }
}

// P4: build boundary value keys (gather x), stage-1 refine, sparse exact top-K
__global__ void __launch_bounds__(1024) k_topk(const float* __restrict__ x) {
    __shared__ int s_cnt;
    __shared__ int s_done;
    int b = blockIdx.x, side = blockIdx.y;
    int K;
    if (side == 0) {
        int nf = g_nfg[b];
        K = g_deg[b] ? 0 : (nf < 100 ? nf : 100);
    } else {
        K = g_deg[b] ? 0 : 100;
    }
    if (K <= 0) return;
    int N = g_n[side][b];
    if (N > CAPC) N = CAPC;
    const float* xb = x + (size_t)b * HWN;
    int tid = threadIdx.x;
    int need = side ? g_needB[b] : g_needF[b];
    int np = 0;
    ull Tv = 0;
    if (need > 0) {
        np = g_np[side][b];
        if (np > CAPP) np = CAPP;
        // build exact value keys for boundary pixels
        for (int i = tid; i < np; i += 1024) {
            int pix = (int)(g_pr[side][b][i] & 0xFFFFFFFFull);
            u32 vbits = __float_as_uint(__fadd_rn(xb[pix], 1e-8f));
            g_p1[side][b][i] = side ? ~((((ull)vbits) << 32) | (u32)pix)
                                    : ((((ull)vbits) << 32) | (u32)(HWN - 1 - pix));
        }
        __syncthreads();
        Tv = radix_kth_largest(g_p1[side][b], np, need);
    }
    const ull* recs = g_rec[side][b];
    const ull* bkeys = g_p1[side][b];
    const ull* brecs = g_pr[side][b];
    ull* sk = g_sk[side][b];
    if (tid == 0) s_done = 0;
    __syncthreads();
    for (int tier = 0; tier < 3; tier++) {
        if (s_done) break;
        u32 ucut = (tier == 0) ? UCUT0 : (tier == 1) ? UCUT1 : 0u;
        if (tid == 0) s_cnt = 0;
        __syncthreads();
        int tot = N + np;
        for (int i = tid; i < tot; i += 1024) {
            ull r;
            if (i < N) r = recs[i];
            else {
                if (bkeys[i - N] < Tv) continue;
                r = brecs[i - N];
            }
            u32 uhi = (u32)(r >> 32);
            if (uhi >= ucut) {
                float u = __uint_as_float(uhi & 0x7FFFFFFFu);
                int pix = (int)(r & 0xFFFFFFFFull);
                float v = __fadd_rn(xb[pix], 1e-8f);
                float p = side ? (fmaxf(1.0f - v, 0.0f) + 1e-8f) : v;
                float s = logf(p) - logf(-logf(u));
                int pos = atomicAdd(&s_cnt, 1);
                sk[pos] = (((ull)fmono(s)) << 32) | (u32)(HWN - 1 - pix);
            }
        }
        __syncthreads();
        int cnt = s_cnt;
        bool ok = false;
        ull T = 0;
        if (cnt >= K) {
            T = radix_kth_largest(sk, cnt, K);
            if (tier == 2) ok = true;
            else {
                float sK = fmono_inv((u32)(T >> 32));
                float edge = (tier == 0) ? 0.984375f : 0.75f;
                float gc = -logf(-logf(edge));
                ok = (sK > gc);
            }
        }
        if (ok) {
            ull* seed = g_seed[side][b];
            for (int i = tid; i < cnt; i += 1024)
                if (sk[i] >= T) mark_seed(seed, HWN - 1 - (int)(sk[i] & 0xFFFFFFFFull));
            if (tid == 0) s_done = 1;
        }
        __syncthreads();
    }
}

// P5: 3x3 dilation + compose; 16-row bands, float4 stores
__global__ void __launch_bounds__(256) k_output(float* __restrict__ out) {
    __shared__ ull sv[2][16][8], sh[2][16][8];
    int b = blockIdx.x >> 5, band = blockIdx.x & 31, r0 = band * 16;
    int t = threadIdx.x;
    {
        int side = t >> 7, rr = (t >> 3) & 15, w = t & 7;
        int r = r0 + rr;
        const ull* sd = g_seed[side][b];
        ull v = sd[r * 8 + w];
        if (r > 0)   v |= sd[(r - 1) * 8 + w];
        if (r < 511) v |= sd[(r + 1) * 8 + w];
        sv[side][rr][w] = v;
    }
    __syncthreads();
    {
        int side = t >> 7, rr = (t >> 3) & 15, w = t & 7;
        ull m = sv[side][rr][w];
        ull h = m | (m << 1) | (m >> 1);
        if (w > 0) h |= sv[side][rr][w - 1] >> 63;
        if (w < 7) h |= sv[side][rr][w + 1] << 63;
        sh[side][rr][w] = h;
    }
    __syncthreads();
    int rr = t >> 4, c0 = (t & 15) * 32;
    int w = c0 >> 6, half = c0 & 32;
    u32 fb = (u32)(sh[0][rr][w] >> half);
    u32 gb = (u32)(sh[1][rr][w] >> half);
    float4* o4 = (float4*)(out + (size_t)b * HWN + (size_t)(r0 + rr) * WN + c0);
#pragma unroll
    for (int j = 0; j < 8; j++) {
        float vv[4];
#pragma unroll
        for (int k = 0; k < 4; k++) {
            int bit = j * 4 + k;
            int f = (fb >> bit) & 1, g = (gb >> bit) & 1;
            vv[k] = (f && !g) ? 1.0f : ((g && !f) ? 0.0f : -255.0f);
        }
        o4[j] = make_float4(vv[0], vv[1], vv[2], vv[3]);
    }
}

extern "C" void kernel_launch(void* const* d_in, const int* in_sizes, int n_in,
                              void* d_out, int out_size) {
    (void)out_size;
    const float* big[3] = {nullptr, nullptr, nullptr};
    const float* rt = nullptr;
    int nb = 0;
    for (int i = 0; i < n_in && i < 4; i++) {
        if (in_sizes[i] == BN) rt = (const float*)d_in[i];
        else if (nb < 3)       big[nb++] = (const float*)d_in[i];
    }
    const float* x   = big[0];
    const float* ufg = big[1];
    const float* ubg = big[2];
    float* out = (float*)d_out;

    const int ERODE_SMEM = 8192 * 8 + 1024 * 68;   // 135168
    cudaFuncSetAttribute(k_erode, cudaFuncAttributeMaxDynamicSharedMemorySize, ERODE_SMEM);

    k_zero<<<512, 256>>>();
    k_prep<<<BN * 16, 256>>>(x, rt);
    k_erode<<<BN, 1024, ERODE_SMEM>>>(x);
    k_score<<<BN * 16, 256>>>(ufg, ubg);
    k_topk<<<dim3(BN, 2), 1024>>>(x);
    k_output<<<2048, 256>>>(out);
}

// round 17
// speedup vs baseline: 2.4485x; 1.0680x over previous
#include <cuda_runtime.h>
#include <cuda_bf16.h>
#include <math.h>

#define BN    64
#define HN    512
#define WN    512
#define HWN   262144
#define NBGC  78643
#define CAPP  16384
#define CAPC  131072

#define UCUT0 0xBF7C0000u   // fmono(0.984375f)
#define UCUT1 0xBF400000u   // fmono(0.75f)
#define UBITS1 0x3F400000u  // raw bits of 0.75f

typedef unsigned long long ull;
typedef unsigned int       u32;
typedef unsigned char      u8;

__device__ ull g_pre[BN][HN * 8];
__device__ ull g_er [BN][HN * 8];
__device__ u32 g_bin8[BN][HWN / 4];   // packed 4x u8 bins per u32
__device__ u32 g_ch_all[BN][64];
__device__ u32 g_minb[BN], g_maxb[BN];
__device__ int g_nfg[BN], g_deg[BN];
__device__ int g_BbC[BN], g_needB[BN];
__device__ int g_BfC[BN], g_needF[BN];
__device__ int g_done1[BN];
__device__ ull g_rec[2][BN][CAPC];    // combined candidate records (u|msb)<<32|pix
__device__ int g_n[2][BN];
__device__ ull g_p1[2][BN][CAPP];     // boundary value keys (built in topk)
__device__ ull g_sk[2][BN][CAPC];     // score-key / fallback scratch
__device__ int g_flag[2][BN];
__device__ ull g_seed[2][BN][HN * 8];

__device__ __forceinline__ int cbin(float v) {
    int k = (int)(v * 64.0f);
    return k > 63 ? 63 : k;
}
__device__ __forceinline__ u32 fmono(float f) {
    u32 b = __float_as_uint(f);
    return (b & 0x80000000u) ? ~b : (b | 0x80000000u);
}
__device__ __forceinline__ float fmono_inv(u32 m) {
    u32 b = (m & 0x80000000u) ? (m ^ 0x80000000u) : ~m;
    return __uint_as_float(b);
}
__device__ __forceinline__ void mark_seed(ull* seedimg, int pix) {
    atomicOr(&seedimg[(pix >> 9) * 8 + ((pix & 511) >> 6)], 1ull << (pix & 63));
}

__device__ __forceinline__ ull radix_kth_largest(const ull* __restrict__ list,
                                                 int cnt, int need) {
    __shared__ u32 rh[256];
    __shared__ ull s_pref;
    __shared__ int s_nd;
    int tid = threadIdx.x;
    if (tid == 0) { s_pref = 0ull; s_nd = need; }
    __syncthreads();
    for (int by = 7; by >= 0; --by) {
        for (int j = tid; j < 256; j += blockDim.x) rh[j] = 0;
        __syncthreads();
        ull mask = (by == 7) ? 0ull : (~0ull << (8 * (by + 1)));
        ull pref = s_pref;
        for (int i = tid; i < cnt; i += blockDim.x) {
            ull k = list[i];
            if (((k ^ pref) & mask) == 0ull)
                atomicAdd(&rh[(int)((k >> (8 * by)) & 255ull)], 1u);
        }
        __syncthreads();
        if (tid == 0) {
            int nd = s_nd; int cum = 0; int sel = 0;
            for (int v = 255; v >= 0; --v) {
                u32 c = rh[v];
                if (cum + (int)c >= nd) { sel = v; s_nd = nd - cum; break; }
                cum += c;
            }
            s_pref = pref | (((ull)sel) << (8 * by));
        }
        __syncthreads();
    }
    return s_pref;
}

__global__ void k_zero() {
    int i = blockIdx.x * blockDim.x + threadIdx.x;
    int stride = gridDim.x * blockDim.x;
    ull* seeds = &g_seed[0][0][0];
    for (int j = i; j < 2 * BN * HN * 8; j += stride) seeds[j] = 0ull;
    u32* h1 = &g_ch_all[0][0];
    for (int j = i; j < BN * 64; j += stride) h1[j] = 0;
    if (i < BN) {
        g_n[0][i] = 0;  g_n[1][i] = 0;
        g_done1[i] = 0;
        g_flag[0][i] = 0; g_flag[1][i] = 0;
        g_minb[i] = 0xFFFFFFFFu; g_maxb[i] = 0u;
    }
}

// P1: x -> pre-erosion bitmap, minmax, 64-bin hist, packed bin array
__global__ void __launch_bounds__(256) k_prep(const float* __restrict__ x,
                                              const float* __restrict__ rt) {
    __shared__ u8 sc[256 * 68];
    __shared__ u32 smn[8], smx[8];
    int b = blockIdx.x >> 4;
    int chunk = blockIdx.x & 15;
    int tid = threadIdx.x, lane = tid & 31;
    for (int j = tid; j < 256 * 68 / 4; j += 256) ((u32*)sc)[j] = 0;
    float th = rt[b];
    float thA = (th == 0.0f) ? 1.0f : ((th == 255.0f) ? 254.0f : th);
    u32 mn = 0xFFFFFFFFu, mx = 0u;
    const float4* xb4 = (const float4*)(x + (size_t)b * HWN);
    u32* bm = (u32*)g_pre[b];
    u32* binw = g_bin8[b];
    int base = chunk * 4096;
    __syncthreads();
    float4 xv = xb4[base + tid];
    for (int it = 0; it < 16; it++) {
        int gf4 = base + it * 256 + tid;
        float4 nx;
        if (it < 15) nx = xb4[gf4 + 256];
        float e[4] = {xv.x, xv.y, xv.z, xv.w};
        u32 nib = 0, packed = 0;
#pragma unroll
        for (int k = 0; k < 4; k++) {
            float cam = e[k];
            u32 cb2 = __float_as_uint(cam);
            mn = min(mn, cb2); mx = max(mx, cb2);
            int bin = cbin(__fadd_rn(cam, 1e-8f));
            sc[tid * 68 + bin]++;
            packed |= ((u32)bin) << (8 * k);
            if (floorf(cam * 255.0f) > thA) nib |= (1u << k);
        }
        binw[gf4] = packed;
        u32 vv = nib << (4 * (lane & 7));
        vv |= __shfl_xor_sync(0xFFFFFFFFu, vv, 1);
        vv |= __shfl_xor_sync(0xFFFFFFFFu, vv, 2);
        vv |= __shfl_xor_sync(0xFFFFFFFFu, vv, 4);
        if ((lane & 7) == 0) bm[gf4 >> 3] = vv;
        xv = nx;
    }
    __syncthreads();
    if (tid < 64) {
        u32 s = 0;
        for (int t2 = 0; t2 < 256; t2++) s += sc[t2 * 68 + tid];
        if (s) atomicAdd(&g_ch_all[b][tid], s);
    }
    for (int o = 16; o; o >>= 1) {
        mn = min(mn, __shfl_down_sync(0xFFFFFFFFu, mn, o));
        mx = max(mx, __shfl_down_sync(0xFFFFFFFFu, mx, o));
    }
    if (lane == 0) { smn[tid >> 5] = mn; smx[tid >> 5] = mx; }
    __syncthreads();
    if (tid == 0) {
        for (int w = 1; w < 8; w++) { mn = min(mn, smn[w]); mx = max(mx, smx[w]); }
        atomicMin(&g_minb[b], mn);
        atomicMax(&g_maxb[b], mx);
        __threadfence();
        int d = atomicAdd(&g_done1[b], 1);
        if (d == 15) {
            u32 mnv = atomicMin(&g_minb[b], 0xFFFFFFFFu);
            u32 mxv = atomicMax(&g_maxb[b], 0u);
            g_deg[b] = (mnv == mxv) ? 1 : 0;
            int cum = 0, Bb = 64, nd = 0;
            for (int j = 0; j < 64; j++) {
                int c = (int)atomicAdd(&g_ch_all[b][j], 0u);
                if (cum + c >= NBGC) { Bb = j; nd = NBGC - cum; break; }
                cum += c;
            }
            g_BbC[b] = Bb; g_needB[b] = nd;
        }
    }
}

// P2: 11x11 erosion + roi popcount -> n_fg; fused roi hist + fg coarse scan
__global__ void __launch_bounds__(1024) k_erode(const float* __restrict__ x) {
    extern __shared__ ull dsm[];
    ull* s_pre = dsm;
    ull* s_hb  = dsm + 4096;
    u8*  sc    = (u8*)(dsm + 8192);
    __shared__ int red[32];
    __shared__ int s_nfg;
    __shared__ u32 bh[64];
    int b = blockIdx.x, tid = threadIdx.x, lane = tid & 31;
    for (int i = tid; i < 4096; i += 1024) s_pre[i] = g_pre[b][i];
    __syncthreads();
    for (int i = tid; i < 4096; i += 1024) {
        int w = i & 7;
        ull av = s_pre[i];
        ull lo = w ? s_pre[i - 1] : ~0ull;
        ull hi = (w < 7) ? s_pre[i + 1] : ~0ull;
        ull r = av;
#pragma unroll
        for (int d = 1; d <= 5; d++)
            r &= ((av >> d) | (hi << (64 - d))) & ((av << d) | (lo >> (64 - d)));
        s_hb[i] = r;
    }
    __syncthreads();
    int pc = 0;
    for (int i = tid; i < 4096; i += 1024) {
        int row = i >> 3, w = i & 7;
        ull r = ~0ull;
#pragma unroll
        for (int d = -5; d <= 5; d++) {
            int rr = row + d;
            if (rr >= 0 && rr < HN) r &= s_hb[rr * 8 + w];
        }
        g_er[b][i] = r;
        s_pre[i] = r;
        pc += __popcll(r);
    }
    for (int o = 16; o; o >>= 1) pc += __shfl_down_sync(0xFFFFFFFFu, pc, o);
    if (lane == 0) red[tid >> 5] = pc;
    __syncthreads();
    if (tid == 0) {
        int c = 0;
        for (int w = 0; w < 32; w++) c += red[w];
        int nfg = (int)floorf(0.3f * (float)c);
        g_nfg[b] = nfg;
        s_nfg = nfg;
    }
    __syncthreads();
    int nfg = s_nfg;
    if (nfg > 0) {
        for (int j = tid * 17; j < tid * 17 + 17; j++) ((u32*)sc)[j] = 0;
        __syncthreads();
        const u32* binw = g_bin8[b];
        for (int it = 0; it < 64; it++) {
            int gf4 = it * 1024 + tid;
            int p = gf4 * 4;
            u32 bits4 = (u32)(s_pre[(p >> 9) * 8 + ((p & 511) >> 6)] >> (p & 63)) & 0xFu;
            if (bits4) {
                u32 pk = binw[gf4];
                if (bits4 & 1u) sc[tid * 68 + (pk & 63u)]++;
                if (bits4 & 2u) sc[tid * 68 + ((pk >> 8) & 63u)]++;
                if (bits4 & 4u) sc[tid * 68 + ((pk >> 16) & 63u)]++;
                if (bits4 & 8u) sc[tid * 68 + ((pk >> 24) & 63u)]++;
            }
        }
        __syncthreads();
        if (tid < 64) {
            u32 s = 0;
            for (int t2 = 0; t2 < 1024; t2++) s += sc[t2 * 68 + tid];
            bh[tid] = s;
        }
        __syncthreads();
    }
    if (tid == 0) {
        int Bf = 64, nd = 0;
        if (nfg > 0) {
            int cum = 0;
            for (int j = 63; j >= 0; j--) {
                int c = (int)bh[j];
                if (cum + c >= nfg) { Bf = j; nd = nfg - cum; break; }
                cum += c;
            }
        }
        g_BfC[b] = Bf; g_needF[b] = nd;
    }
}

// P3: streaming classify — ONE combined emit group per side.
// bg: sure records filtered by u>=0.75; boundary always emitted.
// fg: all roi candidates (bin >= BfC), unfiltered.
__global__ void __launch_bounds__(256) k_score(const float* __restrict__ ufg,
                                               const float* __restrict__ ubg) {
    int b = blockIdx.x >> 4;
    int chunk = blockIdx.x & 15;
    int tid = threadIdx.x, lane = tid & 31;
    int BbC = g_BbC[b], BfC = g_BfC[b];
    bool doFg = g_nfg[b] > 0;
    const u32* binw = g_bin8[b];
    const float4* uf4 = (const float4*)(ufg + (size_t)b * HWN);
    const float4* ub4 = (const float4*)(ubg + (size_t)b * HWN);
    const u32* erw = (const u32*)g_er[b];
    int base = chunk * 4096;
    u32 lt = (1u << lane) - 1u;
    u32 pk = binw[base + tid];
    float4 ubv = ub4[base + tid];
    float4 ufv;
    if (doFg) ufv = uf4[base + tid];
    for (int it = 0; it < 16; it++) {
        int gf4 = base + it * 256 + tid;
        u32 npk = 0; float4 nb2, nf;
        if (it < 15) {
            npk = binw[gf4 + 256];
            nb2 = ub4[gf4 + 256];
            if (doFg) nf = uf4[gf4 + 256];
        }
        float eub[4] = {ubv.x, ubv.y, ubv.z, ubv.w};
        int bin[4] = {(int)(pk & 63u), (int)((pk >> 8) & 63u),
                      (int)((pk >> 16) & 63u), (int)((pk >> 24) & 63u)};
        bool pb[4];
        ull recB[4];
#pragma unroll
        for (int k = 0; k < 4; k++) {
            int pix = gf4 * 4 + k;
            u32 ubits = __float_as_uint(eub[k]);
            pb[k] = (bin[k] < BbC) ? (ubits >= UBITS1) : (bin[k] == BbC);
            recB[k] = (((ull)(ubits | 0x80000000u)) << 32) | (u32)pix;
        }
        {   // combined bg emit
            u32 m0 = __ballot_sync(~0u, pb[0]), m1 = __ballot_sync(~0u, pb[1]);
            u32 m2 = __ballot_sync(~0u, pb[2]), m3 = __ballot_sync(~0u, pb[3]);
            int p0 = __popc(m0), p01 = p0 + __popc(m1), p012 = p01 + __popc(m2);
            int tot = p012 + __popc(m3);
            int bse = 0;
            if (lane == 0 && tot) bse = atomicAdd(&g_n[1][b], tot);
            bse = __shfl_sync(~0u, bse, 0);
            if (pb[0]) { int j = bse + __popc(m0 & lt);        if (j < CAPC) g_rec[1][b][j] = recB[0]; }
            if (pb[1]) { int j = bse + p0 + __popc(m1 & lt);   if (j < CAPC) g_rec[1][b][j] = recB[1]; }
            if (pb[2]) { int j = bse + p01 + __popc(m2 & lt);  if (j < CAPC) g_rec[1][b][j] = recB[2]; }
            if (pb[3]) { int j = bse + p012 + __popc(m3 & lt); if (j < CAPC) g_rec[1][b][j] = recB[3]; }
        }
        if (doFg) {
            u32 rbits = (erw[gf4 >> 3] >> ((gf4 & 7) * 4)) & 0xFu;
            float euf[4] = {ufv.x, ufv.y, ufv.z, ufv.w};
            bool pf[4];
            ull recF[4];
#pragma unroll
            for (int k = 0; k < 4; k++) {
                int pix = gf4 * 4 + k;
                int roi = (rbits >> k) & 1;
                pf[k] = roi && (bin[k] >= BfC);
                recF[k] = (((ull)(__float_as_uint(euf[k]) | 0x80000000u)) << 32) | (u32)pix;
            }
            u32 m0 = __ballot_sync(~0u, pf[0]), m1 = __ballot_sync(~0u, pf[1]);
            u32 m2 = __ballot_sync(~0u, pf[2]), m3 = __ballot_sync(~0u, pf[3]);
            int p0 = __popc(m0), p01 = p0 + __popc(m1), p012 = p01 + __popc(m2);
            int tot = p012 + __popc(m3);
            int bse = 0;
            if (lane == 0 && tot) bse = atomicAdd(&g_n[0][b], tot);
            bse = __shfl_sync(~0u, bse, 0);
            if (pf[0]) { int j = bse + __popc(m0 & lt);        if (j < CAPC) g_rec[0][b][j] = recF[0]; }
            if (pf[1]) { int j = bse + p0 + __popc(m1 & lt);   if (j < CAPC) g_rec[0][b][j] = recF[1]; }
            if (pf[2]) { int j = bse + p01 + __popc(m2 & lt);  if (j < CAPC) g_rec[0][b][j] = recF[2]; }
            if (pf[3]) { int j = bse + p012 + __popc(m3 & lt); if (j < CAPC) g_rec[0][b][j] = recF[3]; }
            ufv = nf;
        }
        pk = npk; ubv = nb2;
    }
}

// P4: boundary-key build + stage-1 refine + sparse exact top-K (tiered)
__global__ void __launch_bounds__(1024) k_topk(const float* __restrict__ x) {
    __shared__ int s_cnt, s_np, s_done;
    int b = blockIdx.x, side = blockIdx.y;   // 0=fg, 1=bg
    int tid = threadIdx.x;
    int K;
    if (side == 0) {
        int nf = g_nfg[b];
        K = g_deg[b] ? 0 : (nf < 100 ? nf : 100);
    } else {
        K = g_deg[b] ? 0 : 100;
    }
    if (K <= 0) return;
    int N = g_n[side][b];
    bool of = false;
    if (N > CAPC) { N = CAPC; of = true; }
    const float* xb = x + (size_t)b * HWN;
    int Bc = side ? g_BbC[b] : g_BfC[b];
    int need = side ? g_needB[b] : g_needF[b];
    const ull* recs = g_rec[side][b];
    ull* bk = g_p1[side][b];
    ull* sk = g_sk[side][b];
    ull Tv = ~0ull;
    if (tid == 0) { s_np = 0; s_done = 0; }
    __syncthreads();
    if (need > 0) {
        for (int i = tid; i < N; i += 1024) {
            int pix = (int)(recs[i] & 0xFFFFFFFFull);
            float v = __fadd_rn(xb[pix], 1e-8f);
            if (cbin(v) == Bc) {
                u32 vbits = __float_as_uint(v);
                int p = atomicAdd(&s_np, 1);
                if (p < CAPP)
                    bk[p] = side ? ~((((ull)vbits) << 32) | (u32)pix)
                                 : ((((ull)vbits) << 32) | (u32)(HWN - 1 - pix));
            }
        }
        __syncthreads();
        int np = s_np;
        if (np > CAPP) { np = CAPP; of = true; }
        Tv = radix_kth_largest(bk, np, need);
    }
    if (of) { if (tid == 0) g_flag[side][b] = 1; return; }
    int ntier = side ? 2 : 3;
    for (int tier = 0; tier < ntier; tier++) {
        if (s_done) break;
        u32 ucut = (tier == 0) ? UCUT0 : (tier == 1) ? UCUT1 : 0u;
        if (tid == 0) s_cnt = 0;
        __syncthreads();
        for (int i = tid; i < N; i += 1024) {
            ull r = recs[i];
            u32 uhi = (u32)(r >> 32);
            if (uhi < ucut) continue;
            int pix = (int)(r & 0xFFFFFFFFull);
            float v = __fadd_rn(xb[pix], 1e-8f);
            int bin = cbin(v);
            u32 vbits = __float_as_uint(v);
            bool cand;
            if (side) cand = (bin < Bc) ||
                (bin == Bc && (~((((ull)vbits) << 32) | (u32)pix)) >= Tv);
            else cand = (bin > Bc) ||
                (bin == Bc && ((((ull)vbits) << 32) | (u32)(HWN - 1 - pix)) >= Tv);
            if (!cand) continue;
            float u = __uint_as_float(uhi & 0x7FFFFFFFu);
            float p = side ? (fmaxf(1.0f - v, 0.0f) + 1e-8f) : v;
            float s = logf(p) - logf(-logf(u));
            int pos = atomicAdd(&s_cnt, 1);
            sk[pos] = (((ull)fmono(s)) << 32) | (u32)(HWN - 1 - pix);
        }
        __syncthreads();
        int cnt = s_cnt;
        bool ok = false;
        ull T = 0;
        if (cnt >= K) {
            T = radix_kth_largest(sk, cnt, K);
            if (side == 0 && tier == 2) ok = true;
            else {
                float sK = fmono_inv((u32)(T >> 32));
                float edge = (tier == 0) ? 0.984375f : 0.75f;
                float gc = -logf(-logf(edge));
                ok = (sK > gc + 1e-3f);
            }
        }
        if (ok) {
            ull* seed = g_seed[side][b];
            for (int i = tid; i < cnt; i += 1024)
                if (sk[i] >= T) mark_seed(seed, HWN - 1 - (int)(sk[i] & 0xFFFFFFFFull));
            if (tid == 0) s_done = 1;
        }
        __syncthreads();
    }
    if (side == 1 && !s_done) { if (tid == 0) g_flag[1][b] = 1; }
}

// P5: exact full redo for flagged (img,side); normally immediate return.
__global__ void __launch_bounds__(1024) k_fb(const float* __restrict__ x,
                                             const float* __restrict__ ufg,
                                             const float* __restrict__ ubg) {
    __shared__ u32 rh[256];
    __shared__ ull s_pref; __shared__ int s_nd, s_cnt;
    int b = blockIdx.x, side = blockIdx.y;
    if (!g_flag[side][b]) return;
    int tid = threadIdx.x;
    const float* xb = x + (size_t)b * HWN;
    const float* uu = (side ? ubg : ufg) + (size_t)b * HWN;
    const ull* roi = g_er[b];
    int K, target;
    if (side == 0) {
        int nfg = g_nfg[b];
        K = nfg < 100 ? nfg : 100;
        target = nfg;
        if (K <= 0 || g_deg[b]) return;
    } else {
        if (g_deg[b]) return;
        K = 100; target = NBGC;
    }
    if (tid == 0) { s_pref = 0ull; s_nd = target; }
    __syncthreads();
    for (int by = 7; by >= 0; --by) {
        for (int j = tid; j < 256; j += 1024) rh[j] = 0;
        __syncthreads();
        ull mask = (by == 7) ? 0ull : (~0ull << (8 * (by + 1)));
        ull pref = s_pref;
        for (int pix = tid; pix < HWN; pix += 1024) {
            if (side == 0 && !((roi[(pix >> 9) * 8 + ((pix & 511) >> 6)] >> (pix & 63)) & 1ull))
                continue;
            u32 vbits = __float_as_uint(__fadd_rn(xb[pix], 1e-8f));
            ull key = side ? ~((((ull)vbits) << 32) | (u32)pix)
                           : ((((ull)vbits) << 32) | (u32)(HWN - 1 - pix));
            if (((key ^ pref) & mask) == 0ull)
                atomicAdd(&rh[(int)((key >> (8 * by)) & 255ull)], 1u);
        }
        __syncthreads();
        if (tid == 0) {
            int nd = s_nd, cum = 0, sel = 0;
            for (int v = 255; v >= 0; --v) {
                u32 c = rh[v];
                if (cum + (int)c >= nd) { sel = v; s_nd = nd - cum; break; }
                cum += c;
            }
            s_pref = s_pref | (((ull)sel) << (8 * by));
        }
        __syncthreads();
    }
    ull Tc = s_pref;
    if (tid == 0) s_cnt = 0;
    __syncthreads();
    for (int pix = tid; pix < HWN; pix += 1024) {
        if (side == 0 && !((roi[(pix >> 9) * 8 + ((pix & 511) >> 6)] >> (pix & 63)) & 1ull))
            continue;
        float v = __fadd_rn(xb[pix], 1e-8f);
        u32 vbits = __float_as_uint(v);
        ull key = side ? ~((((ull)vbits) << 32) | (u32)pix)
                       : ((((ull)vbits) << 32) | (u32)(HWN - 1 - pix));
        if (key >= Tc) {
            float u = uu[pix];
            float p = side ? (fmaxf(1.0f - v, 0.0f) + 1e-8f) : v;
            float s = logf(p) - logf(-logf(u));
            int pos = atomicAdd(&s_cnt, 1);
            g_sk[side][b][pos] = (((ull)fmono(s)) << 32) | (u32)(HWN - 1 - pix);
        }
    }
    __syncthreads();
    int cnt = s_cnt;
    ull Ts = radix_kth_largest(g_sk[side][b], cnt, K);
    ull* seed = g_seed[side][b];
    for (int i = tid; i < cnt; i += 1024) {
        ull k = g_sk[side][b][i];
        if (k >= Ts) mark_seed(seed, HWN - 1 - (int)(k & 0xFFFFFFFFull));
    }
}

// P6: 3x3 dilation + compose; 16-row bands, float4 stores
__global__ void __launch_bounds__(256) k_output(float* __restrict__ out) {
    __shared__ ull sv[2][16][8], sh[2][16][8];
    int b = blockIdx.x >> 5, band = blockIdx.x & 31, r0 = band * 16;
    int t = threadIdx.x;
    {
        int side = t >> 7, rr = (t >> 3) & 15, w = t & 7;
        int r = r0 + rr;
        const ull* sd = g_seed[side][b];
        ull v = sd[r * 8 + w];
        if (r > 0)   v |= sd[(r - 1) * 8 + w];
        if (r < 511) v |= sd[(r + 1) * 8 + w];
        sv[side][rr][w] = v;
    }
    __syncthreads();
    {
        int side = t >> 7, rr = (t >> 3) & 15, w = t & 7;
        ull m = sv[side][rr][w];
        ull h = m | (m << 1) | (m >> 1);
        if (w > 0) h |= sv[side][rr][w - 1] >> 63;
        if (w < 7) h |= sv[side][rr][w + 1] << 63;
        sh[side][rr][w] = h;
    }
    __syncthreads();
    int rr = t >> 4, c0 = (t & 15) * 32;
    int w = c0 >> 6, half = c0 & 32;
    u32 fb = (u32)(sh[0][rr][w] >> half);
    u32 gb = (u32)(sh[1][rr][w] >> half);
    float4* o4 = (float4*)(out + (size_t)b * HWN + (size_t)(r0 + rr) * WN + c0);
#pragma unroll
    for (int j = 0; j < 8; j++) {
        float vv[4];
#pragma unroll
        for (int k = 0; k < 4; k++) {
            int bit = j * 4 + k;
            int f = (fb >> bit) & 1, g = (gb >> bit) & 1;
            vv[k] = (f && !g) ? 1.0f : ((g && !f) ? 0.0f : -255.0f);
        }
        o4[j] = make_float4(vv[0], vv[1], vv[2], vv[3]);
    }
}

extern "C" void kernel_launch(void* const* d_in, const int* in_sizes, int n_in,
                              void* d_out, int out_size) {
    (void)out_size;
    const float* big[3] = {nullptr, nullptr, nullptr};
    const float* rt = nullptr;
    int nb = 0;
    for (int i = 0; i < n_in && i < 4; i++) {
        if (in_sizes[i] == BN) rt = (const float*)d_in[i];
        else if (nb < 3)       big[nb++] = (const float*)d_in[i];
    }
    const float* x   = big[0];
    const float* ufg = big[1];
    const float* ubg = big[2];
    float* out = (float*)d_out;

    const int ERODE_SMEM = 8192 * 8 + 1024 * 68;   // 135168
    cudaFuncSetAttribute(k_erode, cudaFuncAttributeMaxDynamicSharedMemorySize, ERODE_SMEM);

    k_zero<<<512, 256>>>();
    k_prep<<<BN * 16, 256>>>(x, rt);
    k_erode<<<BN, 1024, ERODE_SMEM>>>(x);
    k_score<<<BN * 16, 256>>>(ufg, ubg);
    k_topk<<<dim3(BN, 2), 1024>>>(x);
    k_fb<<<dim3(BN, 2), 1024>>>(x, ufg, ubg);
    k_output<<<2048, 256>>>(out);
}